// round 13
// baseline (speedup 1.0000x reference)
#include <cuda_runtime.h>
#include <cuda_fp16.h>
#include <math.h>
#include <stdint.h>

#define BATCH 4096
#define HID 256

// ================= scratch (static device memory; zero-initialized) ==========
__device__ float g_obs_part[BATCH * 1024];
__device__ float g_bias[7 * 1024];
__device__ float g_rp0[BATCH * 2];
__device__ float g_hbuf[7][BATCH * HID];
__device__ float g_cbuf[7][BATCH * HID];
__device__ __half g_obsE[BATCH * 416];       // cols 400..415 zero
__device__ __half g_hh[7][BATCH * 256];
__device__ __half g_samp[5][BATCH * 32];     // cols 16..31 zero
__device__ __half g_Ws[1024 * 288];
__device__ __half g_Wo[1024 * 416];
__device__ __align__(16) uint8_t g_w2pack[9216];   // pre-swizzled conv2 weights (fp16)

__device__ __forceinline__ uint32_t smem_to_u32(const void* p) {
    uint32_t a;
    asm("{ .reg .u64 t; cvta.to.shared.u64 t, %1; cvt.u32.u64 %0, t; }" : "=r"(a) : "l"(p));
    return a;
}

#define LDSM_X4(r0, r1, r2, r3, addr) \
    asm volatile("ldmatrix.sync.aligned.m8n8.x4.shared.b16 {%0,%1,%2,%3}, [%4];" \
                 : "=r"(r0), "=r"(r1), "=r"(r2), "=r"(r3) : "r"(addr))

#define CP16(dst, src) \
    asm volatile("cp.async.cg.shared.global [%0], [%1], 16;" :: "r"(dst), "l"(src))
#define CP_COMMIT() asm volatile("cp.async.commit_group;")
#define CP_WAIT0()  asm volatile("cp.async.wait_group 0;")

__device__ __forceinline__ void mma_f16(float* d, const uint32_t* a, const uint32_t* b) {
    asm volatile("mma.sync.aligned.m16n8k16.row.col.f32.f16.f16.f32 "
                 "{%0,%1,%2,%3}, {%4,%5,%6,%7}, {%8,%9}, {%0,%1,%2,%3};"
                 : "+f"(d[0]), "+f"(d[1]), "+f"(d[2]), "+f"(d[3])
                 : "r"(a[0]), "r"(a[1]), "r"(a[2]), "r"(a[3]), "r"(b[0]), "r"(b[1]));
}

__device__ __forceinline__ float tanh_fast(float x) {
    float e = __expf(2.f * x);
    return 1.f - __fdividef(2.f, e + 1.f);
}

__device__ __forceinline__ uint32_t pkh2(float a, float b) {
    __half2 h2 = __floats2half2_rn(a, b);
    return *reinterpret_cast<uint32_t*>(&h2);
}

__device__ __forceinline__ uint32_t swz32(uint32_t row, uint32_t chunk) {
    return row * 32u + ((chunk ^ ((row >> 2) & 1u)) << 4);
}
__device__ __forceinline__ uint32_t swz64(uint32_t row, uint32_t chunk) {
    return row * 64u + ((chunk ^ ((row >> 1) & 3u)) << 4);
}

// ================= prep: weights (ws, wo, w2 pack) =================
#define NB_WS 1152          // 1024*288/256
#define NB_WO 1664          // 1024*416/256
__global__ void prep_w_kernel(const float* __restrict__ W_hh, const float* __restrict__ W_ih,
                              const float* __restrict__ c2w,
                              __half* __restrict__ ws, __half* __restrict__ wo,
                              uint8_t* __restrict__ w2pack)
{
    int b = blockIdx.x;
    int tid = threadIdx.x;
    if (b < NB_WS) {
        int idx = b * 256 + tid;
        int rr = idx / 288, k = idx % 288;
        int old = (rr & 3) * 256 + (rr >> 2);
        float v = 0.f;
        if (k < 256) v = W_hh[(size_t)old * 256 + k];
        else if (k < 272) v = W_ih[(size_t)old * 432 + 400 + (k - 256)];
        ws[idx] = __float2half_rn(v);
    } else if (b < NB_WS + NB_WO) {
        int idx = (b - NB_WS) * 256 + tid;
        int rr = idx / 416, k = idx % 416;
        int old = (rr & 3) * 256 + (rr >> 2);
        float v = (k < 400) ? W_ih[(size_t)old * 432 + k] : 0.f;
        wo[idx] = __float2half_rn(v);
    } else {
        for (int idx = tid; idx < 4608; idx += 256) {
            int cidx = idx >> 8;
            int koff = cidx >> 1, cih = cidx & 1;
            int rem = idx & 255;
            int co = rem >> 4, ci = rem & 15;
            float v = c2w[(co * 32 + cih * 16 + ci) * 9 + koff];
            uint32_t off = cidx * 512 + swz32(co, ci >> 3) + (ci & 7) * 2;
            *(__half*)(w2pack + off) = __float2half_rn(v);
        }
    }
}

// ================= gather embeddings -> fp16 =================
__global__ void gather_kernel(const int* __restrict__ pid, const int* __restrict__ sid,
                              const int* __restrict__ sid0, const int* __restrict__ sid1,
                              const float* __restrict__ pid_emb, const float* __restrict__ sid_emb,
                              __half* __restrict__ sp)
{
    int t = blockIdx.x * blockDim.x + threadIdx.x;
    if (t >= BATCH * 16) return;
    int i = t >> 4, k = t & 15;
    int d = i * 32 + k;
    const size_t seg = (size_t)BATCH * 32;
    sp[d]           = __float2half_rn(pid_emb[pid[i] * 16 + k]);
    sp[seg + d]     = __float2half_rn(sid_emb[sid[i] * 16 + k]);
    sp[2 * seg + d] = __float2half_rn(sid_emb[sid0[i] * 16 + k]);
    sp[3 * seg + d] = __float2half_rn(sid_emb[sid1[i] * 16 + k]);
}

__global__ void bias_kernel(const float* __restrict__ b_ih, const float* __restrict__ b_hh,
                            const float* __restrict__ addr_emb, const float* __restrict__ W_ih,
                            float* __restrict__ bias)
{
    int aid = blockIdx.x;
    int r = threadIdx.x;
    float s = b_ih[r] + b_hh[r];
    #pragma unroll
    for (int k = 0; k < 16; k++)
        s += addr_emb[aid * 16 + k] * W_ih[(size_t)r * 432 + 416 + k];
    int g = r >> 8, u = r & 255;
    bias[aid * 1024 + u * 4 + g] = s;
}

// ================= encoder: fp16, 2 images/block, double-buffered img, cp.async w2 ========
#define E_IMGA  0        // 16384 fp32 (aliased as s_c2 for image in this buffer)
#define E_IMGB  16384    // 16384
#define E_C1    32768    // 65536
#define E_W2    98304    // 9216
#define E_ZERO  107520   // 64
#define ENC_SMEM_BYTES 107584

__global__ void __launch_bounds__(512, 2) encoder_kernel(
                               const float* __restrict__ obs,
                               const float* __restrict__ c1w, const float* __restrict__ c1b,
                               const float* __restrict__ c2b,
                               const uint8_t* __restrict__ w2pack,
                               __half* __restrict__ obs_emb)
{
    extern __shared__ __align__(16) char smem[];
    uint32_t sb = smem_to_u32(smem);
    int tid = threadIdx.x;
    int lane = tid & 31, w = tid >> 5;   // 16 warps
    int img0 = blockIdx.x * 2;

    // ---- async: w2 pack + image 0 ----
    for (int i = tid; i < 576; i += 512) CP16(sb + E_W2 + i * 16, w2pack + i * 16);
    {
        const uint8_t* src = (const uint8_t*)(obs + (size_t)img0 * 4096);
        for (int i = tid; i < 1024; i += 512) CP16(sb + E_IMGA + i * 16, src + i * 16);
    }
    CP_COMMIT();
    if (tid < 4) ((uint4*)(smem + E_ZERO))[tid] = make_uint4(0, 0, 0, 0);

    // ---- conv1 B frags in registers (once) ----
    int g = lane >> 2, cq = lane & 3;
    int k0c = 2 * cq, k1c = 2 * cq + 1;
    int ky0 = k0c / 3, kx0 = k0c % 3;
    int ky1 = k1c / 3, kx1 = k1c % 3;
    uint32_t b1[4][2];
    #pragma unroll
    for (int j = 0; j < 4; j++) {
        int n = j * 8 + g;
        b1[j][0] = pkh2(c1w[n * 9 + k0c], c1w[n * 9 + k1c]);
        b1[j][1] = pkh2((cq == 0) ? c1w[n * 9 + 8] : 0.f, 0.f);
    }
    float bia1a[4], bia1b[4];
    #pragma unroll
    for (int j = 0; j < 4; j++) {
        int cc = j * 8 + cq * 2;
        bia1a[j] = c1b[cc];
        bia1b[j] = c1b[cc + 1];
    }
    // conv2 per-thread constants
    int p2 = w * 16 + (lane & 15);
    int oy2 = p2 >> 4, ox2 = p2 & 15;
    int khalf = lane >> 4;
    int nrow = (lane & 7) + ((lane >> 4) << 3);
    uint32_t chB = (lane >> 3) & 1;
    uint32_t boff = swz32(nrow, chB);
    uint32_t zbase = sb + (uint32_t)E_ZERO + (uint32_t)khalf * 16u;
    float c2bia0, c2bia1;
    {
        int co0 = (lane & 3) * 2;
        c2bia0 = c2b[co0];          // for j tile 0 (co = 0..7 range) -- adjusted per j below
        c2bia1 = c2b[co0 + 1];
    }

    for (int it = 0; it < 2; it++) {
        int img = img0 + it;
        float* s_img = (float*)(smem + (it ? E_IMGB : E_IMGA));
        CP_WAIT0();
        __syncthreads();

        // ---- conv1: warp-local, 4 m16 tiles per warp ----
        #pragma unroll
        for (int t = 0; t < 4; t++) {
            int base = w * 64 + t * 16;
            int p0 = base + g, p1 = p0 + 8;
            int oy0 = p0 >> 5, ox0 = p0 & 31;
            int oy1 = p1 >> 5, ox1 = p1 & 31;
            int iy00 = 2 * oy0 - 1 + ky0, ix00 = 2 * ox0 - 1 + kx0;
            int iy01 = 2 * oy0 - 1 + ky1, ix01 = 2 * ox0 - 1 + kx1;
            int iy10 = 2 * oy1 - 1 + ky0, ix10 = 2 * ox1 - 1 + kx0;
            int iy11 = 2 * oy1 - 1 + ky1, ix11 = 2 * ox1 - 1 + kx1;
            float v00 = (iy00 >= 0 && ix00 >= 0) ? s_img[iy00 * 64 + ix00] : 0.f;
            float v01 = (iy01 >= 0 && ix01 >= 0) ? s_img[iy01 * 64 + ix01] : 0.f;
            float v10 = (iy10 >= 0 && ix10 >= 0) ? s_img[iy10 * 64 + ix10] : 0.f;
            float v11 = (iy11 >= 0 && ix11 >= 0) ? s_img[iy11 * 64 + ix11] : 0.f;
            float v08 = (cq == 0) ? s_img[(2 * oy0 + 1) * 64 + (2 * ox0 + 1)] : 0.f;
            float v18 = (cq == 0) ? s_img[(2 * oy1 + 1) * 64 + (2 * ox1 + 1)] : 0.f;
            uint32_t a[4];
            a[0] = pkh2(v00, v01);
            a[1] = pkh2(v10, v11);
            a[2] = pkh2(v08, 0.f);
            a[3] = pkh2(v18, 0.f);

            float acc[4][4];
            #pragma unroll
            for (int j = 0; j < 4; j++)
                #pragma unroll
                for (int q = 0; q < 4; q++) acc[j][q] = 0.f;
            #pragma unroll
            for (int j = 0; j < 4; j++) mma_f16(acc[j], a, b1[j]);

            #pragma unroll
            for (int j = 0; j < 4; j++) {
                #pragma unroll
                for (int rh = 0; rh < 2; rh++) {
                    int pos = base + g + rh * 8;
                    float v0 = fmaxf(acc[j][rh * 2 + 0] + bia1a[j], 0.f);
                    float v1 = fmaxf(acc[j][rh * 2 + 1] + bia1b[j], 0.f);
                    uint32_t addr = swz64((uint32_t)pos, (uint32_t)j) + cq * 4;
                    *(uint32_t*)(smem + E_C1 + addr) = pkh2(v0, v1);
                }
            }
        }
        __syncthreads();   // C1 ready; img reads done
        if (it == 0) {
            const uint8_t* src = (const uint8_t*)(obs + (size_t)(img0 + 1) * 4096);
            for (int i = tid; i < 1024; i += 512) CP16(sb + E_IMGB + i * 16, src + i * 16);
            CP_COMMIT();
        }

        // ---- conv2 ----
        float acc2[2][4];
        #pragma unroll
        for (int j = 0; j < 2; j++)
            #pragma unroll
            for (int q = 0; q < 4; q++) acc2[j][q] = 0.f;
        #pragma unroll
        for (int koff = 0; koff < 9; koff++) {
            const int ky = koff / 3, kx = koff % 3;
            int iy = 2 * oy2 - 1 + ky, ix = 2 * ox2 - 1 + kx;
            bool valid = (iy >= 0 && iy < 32 && ix >= 0 && ix < 32);
            int c1pos = iy * 32 + ix;
            uint32_t rbase = (uint32_t)c1pos * 64u;
            uint32_t rx = ((uint32_t)(c1pos >> 1) & 3u) << 4;
            #pragma unroll
            for (int cih = 0; cih < 2; cih++) {
                uint32_t chunkA = (uint32_t)(cih * 2 + khalf);
                uint32_t offA = rbase + ((chunkA << 4) ^ rx);
                uint32_t aA = valid ? (sb + E_C1 + offA) : zbase;
                uint32_t bb = sb + (uint32_t)(E_W2) + (uint32_t)(koff * 2 + cih) * 512u + boff;
                uint32_t a[4], bh[2][2];
                LDSM_X4(a[0], a[1], a[2], a[3], aA);
                LDSM_X4(bh[0][0], bh[0][1], bh[1][0], bh[1][1], bb);
                mma_f16(acc2[0], a, bh[0]);
                mma_f16(acc2[1], a, bh[1]);
            }
        }
        {
            float* s_c2 = (float*)(smem + (it ? E_IMGB : E_IMGA));
            #pragma unroll
            for (int j = 0; j < 2; j++) {
                int co = j * 8 + (lane & 3) * 2;
                float bia0 = c2b[co], bia1 = c2b[co + 1];
                #pragma unroll
                for (int rh = 0; rh < 2; rh++) {
                    int pos = w * 16 + (lane >> 2) + rh * 8;
                    float v0 = fmaxf(acc2[j][rh * 2 + 0] + bia0, 0.f);
                    float v1 = fmaxf(acc2[j][rh * 2 + 1] + bia1, 0.f);
                    *(float2*)(s_c2 + pos * 16 + co) = make_float2(v0, v1);
                }
            }
        }
        __syncthreads();
        {
            const float* s_c2 = (const float*)(smem + (it ? E_IMGB : E_IMGA));
            if (tid < 400) {
                int c = tid / 25; int r = tid % 25; int i = r / 5; int j = r % 5;
                float s = 0.f;
                #pragma unroll
                for (int dy = 0; dy < 3; dy++)
                    #pragma unroll
                    for (int dx = 0; dx < 3; dx++)
                        s += s_c2[((3 * i + dy) * 16 + (3 * j + dx)) * 16 + c];
                obs_emb[(size_t)img * 416 + tid] = __float2half_rn(s * (1.f / 9.f));
            }
        }
        __syncthreads();   // pool reads done before buffer reuse / exit
    }
}

// ============ mma.sync fp16 GEMM; modes: 0 raw, 1 lstm, 2 dual-bias, 3 merged-M, 4 raw+step0 =====
#define SROW 80
#define GBUF (128 * SROW)
#define GSTAGE (2 * GBUF)
#define GEMM_SMEM_BYTES (2 * GSTAGE)

__global__ void __launch_bounds__(256, 2) gemm_mma_kernel(
    const __half* __restrict__ A1, int strideA, int KA,
    const __half* __restrict__ S1,
    const __half* __restrict__ W1, int strideB,
    int nchunks, int mode,
    const float* __restrict__ obs_part, const float* __restrict__ bias,
    const float* __restrict__ bias_b,
    const float* __restrict__ c_in,
    float* __restrict__ outD, float* __restrict__ c_out,
    __half* __restrict__ h_out, float* __restrict__ h0f)
{
    extern __shared__ __align__(16) char smc[];
    uint32_t sb = smem_to_u32(smc);

    int tid = threadIdx.x;
    int lane = tid & 31, wid = tid >> 5;
    int wm = wid & 3, wn = wid >> 2;
    int m0 = blockIdx.x * 128;
    int n0 = blockIdx.y * 128;

    int lrow = tid >> 1, lhalf = tid & 1;
    const __half* A_row = A1 + (size_t)(m0 + lrow) * strideA;
    const __half* S_row = S1 ? S1 + (size_t)(m0 + lrow) * 32 : nullptr;
    const __half* W_row = W1 + (size_t)(n0 + lrow) * strideB;

    float acc[2][8][4];
    #pragma unroll
    for (int i = 0; i < 2; i++)
        #pragma unroll
        for (int j = 0; j < 8; j++)
            #pragma unroll
            for (int r = 0; r < 4; r++) acc[i][j][r] = 0.f;

    uint32_t dstA = lrow * SROW + lhalf * 32;

    auto prefetch = [&](int c, int stage) {
        uint32_t sbase = sb + stage * GSTAGE;
        int col = c * 32 + lhalf * 16;
        const __half* pa = (col < KA) ? (A_row + col) : (S_row + (col - KA));
        uint32_t ad = sbase + dstA;
        CP16(ad, pa); CP16(ad + 16, pa + 8);
        const __half* pw = W_row + c * 32 + lhalf * 16;
        CP16(ad + GBUF, pw); CP16(ad + GBUF + 16, pw + 8);
        CP_COMMIT();
    };

    prefetch(0, 0);

    for (int c = 0; c < nchunks; c++) {
        CP_WAIT0();
        __syncthreads();
        if (c + 1 < nchunks) prefetch(c + 1, (c + 1) & 1);

        uint32_t sbase = sb + (c & 1) * GSTAGE;
        uint32_t baseA = sbase, baseB = sbase + GBUF;

        #pragma unroll
        for (int s = 0; s < 2; s++) {
            uint32_t a[2][4], b[8][2];
            int rA = wm * 32 + (lane & 15);
            int cA = s * 32 + ((lane >> 4) << 4);
            uint32_t adA0 = rA * SROW + cA;
            uint32_t adA1 = (rA + 16) * SROW + cA;
            int rB = wn * 64 + ((lane >> 4) << 3) + (lane & 7);
            int cB = s * 32 + (((lane >> 3) & 1) << 4);

            LDSM_X4(a[0][0], a[0][1], a[0][2], a[0][3], baseA + adA0);
            LDSM_X4(a[1][0], a[1][1], a[1][2], a[1][3], baseA + adA1);
            #pragma unroll
            for (int p = 0; p < 4; p++)
                LDSM_X4(b[2 * p][0], b[2 * p][1], b[2 * p + 1][0], b[2 * p + 1][1],
                        baseB + (rB + 16 * p) * SROW + cB);
            #pragma unroll
            for (int mi = 0; mi < 2; mi++)
                #pragma unroll
                for (int nj = 0; nj < 8; nj++) mma_f16(acc[mi][nj], a[mi], b[nj]);
        }
        __syncthreads();
    }

    #pragma unroll
    for (int mi = 0; mi < 2; mi++) {
        #pragma unroll
        for (int nj = 0; nj < 8; nj++) {
            int colg = n0 + wn * 64 + 8 * nj + 2 * (lane & 3);
            #pragma unroll
            for (int rh = 0; rh < 2; rh++) {
                int row = m0 + wm * 32 + mi * 16 + (lane >> 2) + 8 * rh;
                float v0 = acc[mi][nj][rh * 2 + 0];
                float v1 = acc[mi][nj][rh * 2 + 1];
                if (mode == 0 || mode == 4) {
                    float2* dst = (float2*)(outD + (size_t)row * 1024 + colg);
                    *dst = make_float2(v0, v1);
                    if (mode == 4) {
                        float g0 = __shfl_xor_sync(0xffffffffu, v0, 1);
                        float g1 = __shfl_xor_sync(0xffffffffu, v1, 1);
                        if ((lane & 1) == 0) {
                            int unit = colg >> 2;
                            size_t d = (size_t)row * 256 + unit;
                            float4 b4 = *(const float4*)(bias + colg);
                            float gi = v0 + b4.x, gg = g0 + b4.z, go = g1 + b4.w;
                            float si = 1.f / (1.f + __expf(-gi));
                            float so = 1.f / (1.f + __expf(-go));
                            float c2 = si * tanh_fast(gg);
                            float hv = so * tanh_fast(c2);
                            h0f[d] = hv;
                            c_out[d] = c2;
                            h_out[d] = __float2half_rn(hv);
                        }
                    }
                } else {
                    float2 op = *(const float2*)(obs_part + (size_t)(row & (BATCH - 1)) * 1024 + colg);
                    v0 += op.x;
                    v1 += op.y;
                    float g0 = __shfl_xor_sync(0xffffffffu, v0, 1);
                    float g1 = __shfl_xor_sync(0xffffffffu, v1, 1);
                    if ((lane & 1) == 0) {
                        int unit = colg >> 2;
                        float cprev = c_in[(size_t)row * 256 + unit];
                        size_t d = (size_t)row * 256 + unit;
                        const float* bp = (mode == 3 && row >= BATCH) ? bias_b : bias;
                        float4 b4 = *(const float4*)(bp + colg);
                        {
                            float gi = v0 + b4.x, gf = v1 + b4.y, gg = g0 + b4.z, go = g1 + b4.w;
                            float si = 1.f / (1.f + __expf(-gi));
                            float sf = 1.f / (1.f + __expf(-gf));
                            float so = 1.f / (1.f + __expf(-go));
                            float c2 = sf * cprev + si * tanh_fast(gg);
                            float hv = so * tanh_fast(c2);
                            outD[d] = hv;
                            c_out[d] = c2;
                            h_out[d] = __float2half_rn(hv);
                        }
                        if (mode == 2) {
                            float4 b4b = *(const float4*)(bias_b + colg);
                            size_t d2 = d + (size_t)BATCH * 256;
                            float gi = v0 + b4b.x, gf = v1 + b4b.y, gg = g0 + b4b.z, go = g1 + b4b.w;
                            float si = 1.f / (1.f + __expf(-gi));
                            float sf = 1.f / (1.f + __expf(-gf));
                            float so = 1.f / (1.f + __expf(-go));
                            float c2 = sf * cprev + si * tanh_fast(gg);
                            float hv = so * tanh_fast(c2);
                            outD[d2] = hv;
                            c_out[d2] = c2;
                            h_out[d2] = __float2half_rn(hv);
                        }
                    }
                }
            }
        }
    }
}

// ================= mid-chain head (rp0 only) =================
__global__ void head_kernel(const float* __restrict__ h, const float* __restrict__ W,
                            const float* __restrict__ bvec,
                            const float* __restrict__ eps, float* __restrict__ out, int off,
                            float* __restrict__ rp_store)
{
    __shared__ float sW[4 * 256];
    __shared__ float sb[4];
    int tid = threadIdx.x;
    int lane = tid & 31, w = tid >> 5;
    for (int i = tid; i < 1024; i += 256) sW[i] = W[i];
    if (tid < 4) sb[tid] = bvec[tid];
    __syncthreads();

    int rowbase = blockIdx.x * 32 + w * 4;
    for (int rr = 0; rr < 4; rr++) {
        int row = rowbase + rr;
        const float* hp = h + (size_t)row * 256;
        float p0 = 0.f, p1 = 0.f, p2 = 0.f, p3 = 0.f;
        #pragma unroll
        for (int t = 0; t < 8; t++) {
            int k = lane + 32 * t;
            float hv = hp[k];
            p0 += hv * sW[k];
            p1 += hv * sW[256 + k];
            p2 += hv * sW[512 + k];
            p3 += hv * sW[768 + k];
        }
        #pragma unroll
        for (int o = 16; o; o >>= 1) {
            p0 += __shfl_xor_sync(0xffffffffu, p0, o);
            p1 += __shfl_xor_sync(0xffffffffu, p1, o);
            p2 += __shfl_xor_sync(0xffffffffu, p2, o);
            p3 += __shfl_xor_sync(0xffffffffu, p3, o);
        }
        if (lane == 0) {
            float v0 = p0 + sb[0], v1 = p1 + sb[1], v2 = p2 + sb[2], v3 = p3 + sb[3];
            float o0 = v0 + __expf(v2) * eps[row * 2 + 0];
            float o1 = v1 + __expf(v3) * eps[row * 2 + 1];
            out[(size_t)row * 15 + off + 0] = o0;
            out[(size_t)row * 15 + off + 1] = o1;
            rp_store[row * 2 + 0] = o0;
            rp_store[row * 2 + 1] = o1;
        }
    }
}

// ================= mega head: 6 heads in one kernel =================
__global__ void heads_kernel(const float* __restrict__ hb,
                             const float* __restrict__ pid_w, const float* __restrict__ pid_b,
                             const float* __restrict__ sid_w, const float* __restrict__ sid_b,
                             const float* __restrict__ rp_w, const float* __restrict__ rp_b,
                             const float* __restrict__ eps_rp, const float* __restrict__ eps_rp1,
                             float* __restrict__ out)
{
    __shared__ float sW[2304];
    __shared__ float sB[12];
    int tid = threadIdx.x;
    int lane = tid & 31, w = tid >> 5;
    for (int i = tid; i < 768; i += 256) sW[i] = pid_w[i];
    for (int i = tid; i < 512; i += 256) sW[768 + i] = sid_w[i];
    for (int i = tid; i < 1024; i += 256) sW[1280 + i] = rp_w[i];
    if (tid < 3) sB[tid] = pid_b[tid];
    if (tid < 2) sB[4 + tid] = sid_b[tid];
    if (tid < 4) sB[8 + tid] = rp_b[tid];
    __syncthreads();

    const int Hidx[6] = {0, 1, 3, 2, 4, 6};
    const int Wof[6]  = {0, 768, 1280, 768, 768, 1280};
    const int Bof[6]  = {0, 4, 8, 4, 4, 8};
    const int Nout[6] = {3, 2, 4, 2, 2, 4};
    const int Off[6]  = {0, 3, 5, 7, 9, 13};

    int rowbase = blockIdx.x * 32 + w * 4;
    for (int rr = 0; rr < 4; rr++) {
        int row = rowbase + rr;
        #pragma unroll
        for (int e = 0; e < 6; e++) {
            const float* hp = hb + (size_t)Hidx[e] * BATCH * 256 + (size_t)row * 256;
            int wof = Wof[e];
            float p0 = 0.f, p1 = 0.f, p2 = 0.f, p3 = 0.f;
            #pragma unroll
            for (int t = 0; t < 8; t++) {
                int k = lane + 32 * t;
                float hv = hp[k];
                p0 += hv * sW[wof + k];
                p1 += hv * sW[wof + 256 + k];
                if (Nout[e] > 2) p2 += hv * sW[wof + 512 + k];
                if (Nout[e] > 3) p3 += hv * sW[wof + 768 + k];
            }
            #pragma unroll
            for (int o = 16; o; o >>= 1) {
                p0 += __shfl_xor_sync(0xffffffffu, p0, o);
                p1 += __shfl_xor_sync(0xffffffffu, p1, o);
                p2 += __shfl_xor_sync(0xffffffffu, p2, o);
                p3 += __shfl_xor_sync(0xffffffffu, p3, o);
            }
            if (lane == 0) {
                int off = Off[e];
                float b0 = sB[Bof[e]], b1 = sB[Bof[e] + 1];
                if (Nout[e] == 4) {
                    const float* ee = (e == 2) ? eps_rp : eps_rp1;
                    float v0 = p0 + b0, v1 = p1 + b1;
                    float v2 = p2 + sB[Bof[e] + 2], v3 = p3 + sB[Bof[e] + 3];
                    out[(size_t)row * 15 + off + 0] = v0 + __expf(v2) * ee[row * 2 + 0];
                    out[(size_t)row * 15 + off + 1] = v1 + __expf(v3) * ee[row * 2 + 1];
                } else {
                    out[(size_t)row * 15 + off + 0] = p0 + b0;
                    out[(size_t)row * 15 + off + 1] = p1 + b1;
                    if (Nout[e] > 2) out[(size_t)row * 15 + off + 2] = p2 + sB[Bof[e] + 2];
                }
            }
        }
    }
}

// ================= batched MLP =================
#define MLP_SMEM_FLOATS (200 + 104 + 100 * 101 + 104 + 16 * 101 + 16 + 2 * 32 * 104)
__global__ void mlp_kernel(const float* __restrict__ rp0,
                           const float* __restrict__ w1, const float* __restrict__ b1,
                           const float* __restrict__ w2, const float* __restrict__ b2,
                           const float* __restrict__ w3, const float* __restrict__ b3,
                           __half* __restrict__ emb)
{
    extern __shared__ float ms[];
    float* sw1 = ms;
    float* sb1 = sw1 + 200;
    float* sw2 = sb1 + 104;
    float* sb2 = sw2 + 100 * 101;
    float* sw3 = sb2 + 104;
    float* sb3 = sw3 + 16 * 101;
    float* z1  = sb3 + 16;
    float* z2  = z1 + 32 * 104;
    int tid = threadIdx.x;
    int r0 = blockIdx.x * 32;

    for (int i = tid; i < 200; i += 256) sw1[i] = w1[i];
    if (tid < 100) { sb1[tid] = b1[tid]; sb2[tid] = b2[tid]; }
    if (tid < 16) sb3[tid] = b3[tid];
    for (int i = tid; i < 10000; i += 256) { int u = i / 100, k = i - u * 100; sw2[u * 101 + k] = w2[i]; }
    for (int i = tid; i < 1600; i += 256) { int o = i / 100, k = i - o * 100; sw3[o * 101 + k] = w3[i]; }
    __syncthreads();

    for (int t = tid; t < 3200; t += 256) {
        int row = t / 100, u = t - row * 100;
        float x0 = rp0[(r0 + row) * 2], x1 = rp0[(r0 + row) * 2 + 1];
        z1[row * 104 + u] = tanh_fast(sb1[u] + sw1[u * 2] * x0 + sw1[u * 2 + 1] * x1);
    }
    __syncthreads();
    for (int t = tid; t < 3200; t += 256) {
        int row = t / 100, u = t - row * 100;
        float s = sb2[u];
        const float* wr = sw2 + u * 101;
        const float* zr = z1 + row * 104;
        #pragma unroll 4
        for (int k = 0; k < 100; k++) s += wr[k] * zr[k];
        z2[row * 104 + u] = tanh_fast(s);
    }
    __syncthreads();
    for (int t = tid; t < 512; t += 256) {
        int row = t >> 4, o = t & 15;
        float s = sb3[o];
        const float* wr = sw3 + o * 101;
        const float* zr = z2 + row * 104;
        #pragma unroll 4
        for (int k = 0; k < 100; k++) s += wr[k] * zr[k];
        emb[(size_t)(r0 + row) * 32 + o] = __float2half_rn(s);
    }
}

// ================= launch =================
extern "C" void kernel_launch(void* const* d_in, const int* in_sizes, int n_in,
                              void* d_out, int out_size)
{
    const float* obs        = (const float*)d_in[0];
    const int*   program_id = (const int*)d_in[1];
    const int*   shape_id   = (const int*)d_in[2];
    const int*   shape_id_0 = (const int*)d_in[3];
    const int*   shape_id_1 = (const int*)d_in[4];
    const float* eps_rp     = (const float*)d_in[5];
    const float* eps_rp0    = (const float*)d_in[6];
    const float* eps_rp1    = (const float*)d_in[7];
    const float* conv1_w    = (const float*)d_in[8];
    const float* conv1_b    = (const float*)d_in[9];
    const float* conv2_w    = (const float*)d_in[10];
    const float* conv2_b    = (const float*)d_in[11];
    const float* mlp_w1     = (const float*)d_in[12];
    const float* mlp_b1     = (const float*)d_in[13];
    const float* mlp_w2     = (const float*)d_in[14];
    const float* mlp_b2     = (const float*)d_in[15];
    const float* mlp_w3     = (const float*)d_in[16];
    const float* mlp_b3     = (const float*)d_in[17];
    const float* W_ih       = (const float*)d_in[18];
    const float* b_ih       = (const float*)d_in[19];
    const float* W_hh       = (const float*)d_in[20];
    const float* b_hh       = (const float*)d_in[21];
    const float* addr_emb   = (const float*)d_in[22];
    const float* pid_emb    = (const float*)d_in[23];
    const float* sid_emb    = (const float*)d_in[24];
    const float* pid_ext_w  = (const float*)d_in[25];
    const float* pid_ext_b  = (const float*)d_in[26];
    const float* sid_ext_w  = (const float*)d_in[27];
    const float* sid_ext_b  = (const float*)d_in[28];
    const float* rp_ext_w   = (const float*)d_in[29];
    const float* rp_ext_b   = (const float*)d_in[30];
    float* out = (float*)d_out;

    float *obs_part, *bias, *rp0, *hb, *cb;
    __half *ws, *wo, *oe, *hh, *sp;
    uint8_t* w2p;
    cudaGetSymbolAddress((void**)&obs_part, g_obs_part);
    cudaGetSymbolAddress((void**)&bias,     g_bias);
    cudaGetSymbolAddress((void**)&rp0,      g_rp0);
    cudaGetSymbolAddress((void**)&hb,       g_hbuf);
    cudaGetSymbolAddress((void**)&cb,       g_cbuf);
    cudaGetSymbolAddress((void**)&ws,       g_Ws);
    cudaGetSymbolAddress((void**)&wo,       g_Wo);
    cudaGetSymbolAddress((void**)&oe,       g_obsE);
    cudaGetSymbolAddress((void**)&hh,       g_hh);
    cudaGetSymbolAddress((void**)&sp,       g_samp);
    cudaGetSymbolAddress((void**)&w2p,      g_w2pack);
    #define HBUF(i) (hb + (size_t)(i) * BATCH * HID)
    #define CBUF(i) (cb + (size_t)(i) * BATCH * HID)
    #define HH(i)   (hh + (size_t)(i) * BATCH * HID)
    #define SP(i)   (sp + (size_t)(i) * BATCH * 32)

    cudaFuncSetAttribute(encoder_kernel, cudaFuncAttributeMaxDynamicSharedMemorySize, ENC_SMEM_BYTES);
    cudaFuncSetAttribute(gemm_mma_kernel, cudaFuncAttributeMaxDynamicSharedMemorySize, GEMM_SMEM_BYTES);
    cudaFuncSetAttribute(mlp_kernel, cudaFuncAttributeMaxDynamicSharedMemorySize, MLP_SMEM_FLOATS * 4);

    // launch order: encoder is 4th -> profiled
    prep_w_kernel<<<NB_WS + NB_WO + 1, 256>>>(W_hh, W_ih, conv2_w, ws, wo, w2p);
    gather_kernel<<<(BATCH * 16 + 255) / 256, 256>>>(program_id, shape_id, shape_id_0, shape_id_1,
                                                     pid_emb, sid_emb, sp);
    bias_kernel<<<7, 1024>>>(b_ih, b_hh, addr_emb, W_ih, bias);
    encoder_kernel<<<BATCH / 2, 512, ENC_SMEM_BYTES>>>(obs, conv1_w, conv1_b, conv2_b, w2p, oe);

    dim3 ggrid(BATCH / 128, 8);
    // obs_part + fused step0 (mode 4)
    gemm_mma_kernel<<<ggrid, 256, GEMM_SMEM_BYTES>>>(oe, 416, 416, nullptr, wo, 416, 13, 4,
                                    nullptr, bias, nullptr, nullptr,
                                    obs_part, CBUF(0), HH(0), HBUF(0));
    // G12: dual-bias (aid1 -> idx1 h1, aid2 -> idx2 h1b), A=h0, samp=pid
    gemm_mma_kernel<<<ggrid, 256, GEMM_SMEM_BYTES>>>(HH(0), 256, 256, SP(0), ws, 288, 9, 2,
                                    obs_part, bias + 1 * 1024, bias + 2 * 1024, CBUF(0),
                                    HBUF(1), CBUF(1), HH(1), nullptr);
    // G34: merged M=8192; A=[h1;h1b], samp=[sid;sid0], bias aid4 / aid3 -> [h2;h2b]
    {
        dim3 mg(2 * BATCH / 128, 8);
        gemm_mma_kernel<<<mg, 256, GEMM_SMEM_BYTES>>>(HH(1), 256, 256, SP(1), ws, 288, 9, 3,
                                    obs_part, bias + 4 * 1024, bias + 3 * 1024, CBUF(1),
                                    HBUF(3), CBUF(3), HH(3), nullptr);
    }
    // step5: h3b = step(sid1, aid5, h2b=idx4) -> idx5
    gemm_mma_kernel<<<ggrid, 256, GEMM_SMEM_BYTES>>>(HH(4), 256, 256, SP(3), ws, 288, 9, 1,
                                    obs_part, bias + 5 * 1024, nullptr, CBUF(4),
                                    HBUF(5), CBUF(5), HH(5), nullptr);
    // rp0 head (critical)
    head_kernel<<<128, 256>>>(HBUF(5), rp_ext_w, rp_ext_b, eps_rp0, out, 11, rp0);
    mlp_kernel<<<128, 256, MLP_SMEM_FLOATS * 4>>>(rp0, mlp_w1, mlp_b1, mlp_w2, mlp_b2,
                                                  mlp_w3, mlp_b3, SP(4));
    // step6: h4b = step(rp0emb, aid6, h3b=idx5) -> idx6
    gemm_mma_kernel<<<ggrid, 256, GEMM_SMEM_BYTES>>>(HH(5), 256, 256, SP(4), ws, 288, 9, 1,
                                    obs_part, bias + 6 * 1024, nullptr, CBUF(5),
                                    HBUF(6), CBUF(6), HH(6), nullptr);
    // all remaining heads
    heads_kernel<<<128, 256>>>(hb, pid_ext_w, pid_ext_b, sid_ext_w, sid_ext_b,
                               rp_ext_w, rp_ext_b, eps_rp, eps_rp1, out);
}

// round 14
// speedup vs baseline: 1.0540x; 1.0540x over previous
#include <cuda_runtime.h>
#include <cuda_fp16.h>
#include <math.h>
#include <stdint.h>

#define BATCH 4096
#define HID 256

// ================= scratch (static device memory; zero-initialized) ==========
__device__ float g_obs_part[BATCH * 1024];
__device__ float g_bias[7 * 1024];
__device__ float g_rp0[BATCH * 2];
__device__ float g_hbuf[7][BATCH * HID];
__device__ float g_cbuf[7][BATCH * HID];
__device__ __half g_obsE[BATCH * 416];       // cols 400..415 zero
__device__ __half g_hh[7][BATCH * 256];
__device__ __half g_samp[5][BATCH * 32];     // cols 16..31 zero
__device__ __half g_Ws[1024 * 288];
__device__ __half g_Wo[1024 * 416];
__device__ __align__(16) uint8_t g_w2pack[9216];

__device__ __forceinline__ uint32_t smem_to_u32(const void* p) {
    uint32_t a;
    asm("{ .reg .u64 t; cvta.to.shared.u64 t, %1; cvt.u32.u64 %0, t; }" : "=r"(a) : "l"(p));
    return a;
}

#define LDSM_X4(r0, r1, r2, r3, addr) \
    asm volatile("ldmatrix.sync.aligned.m8n8.x4.shared.b16 {%0,%1,%2,%3}, [%4];" \
                 : "=r"(r0), "=r"(r1), "=r"(r2), "=r"(r3) : "r"(addr))

#define CP16(dst, src) \
    asm volatile("cp.async.cg.shared.global [%0], [%1], 16;" :: "r"(dst), "l"(src))
#define CP_COMMIT() asm volatile("cp.async.commit_group;")
#define CP_WAIT0()  asm volatile("cp.async.wait_group 0;")
#define CP_WAIT1()  asm volatile("cp.async.wait_group 1;")

__device__ __forceinline__ void mma_f16(float* d, const uint32_t* a, const uint32_t* b) {
    asm volatile("mma.sync.aligned.m16n8k16.row.col.f32.f16.f16.f32 "
                 "{%0,%1,%2,%3}, {%4,%5,%6,%7}, {%8,%9}, {%0,%1,%2,%3};"
                 : "+f"(d[0]), "+f"(d[1]), "+f"(d[2]), "+f"(d[3])
                 : "r"(a[0]), "r"(a[1]), "r"(a[2]), "r"(a[3]), "r"(b[0]), "r"(b[1]));
}

__device__ __forceinline__ float tanh_fast(float x) {
    float e = __expf(2.f * x);
    return 1.f - __fdividef(2.f, e + 1.f);
}

__device__ __forceinline__ uint32_t pkh2(float a, float b) {
    __half2 h2 = __floats2half2_rn(a, b);
    return *reinterpret_cast<uint32_t*>(&h2);
}

__device__ __forceinline__ uint32_t swz32(uint32_t row, uint32_t chunk) {
    return row * 32u + ((chunk ^ ((row >> 2) & 1u)) << 4);
}
__device__ __forceinline__ uint32_t swz64(uint32_t row, uint32_t chunk) {
    return row * 64u + ((chunk ^ ((row >> 1) & 3u)) << 4);
}

__global__ void bias_kernel(const float* __restrict__ b_ih, const float* __restrict__ b_hh,
                            const float* __restrict__ addr_emb, const float* __restrict__ W_ih,
                            float* __restrict__ bias)
{
    int aid = blockIdx.x;
    int r = threadIdx.x;
    float s = b_ih[r] + b_hh[r];
    #pragma unroll
    for (int k = 0; k < 16; k++)
        s += addr_emb[aid * 16 + k] * W_ih[(size_t)r * 432 + 416 + k];
    int g = r >> 8, u = r & 255;
    bias[aid * 1024 + u * 4 + g] = s;
}

// ================= fused prep: ws + wo + w2pack + gather =================
#define NB_WS 1152
#define NB_WO 1664
#define NB_GA 256
__global__ void prep_all_kernel(const float* __restrict__ W_hh, const float* __restrict__ W_ih,
                                const float* __restrict__ c2w,
                                const int* __restrict__ pid, const int* __restrict__ sid,
                                const int* __restrict__ sid0, const int* __restrict__ sid1,
                                const float* __restrict__ pid_emb, const float* __restrict__ sid_emb,
                                __half* __restrict__ ws, __half* __restrict__ wo,
                                uint8_t* __restrict__ w2pack, __half* __restrict__ sp)
{
    int b = blockIdx.x;
    int tid = threadIdx.x;
    if (b < NB_WS) {
        int idx = b * 256 + tid;
        int rr = idx / 288, k = idx % 288;
        int old = (rr & 3) * 256 + (rr >> 2);
        float v = 0.f;
        if (k < 256) v = W_hh[(size_t)old * 256 + k];
        else if (k < 272) v = W_ih[(size_t)old * 432 + 400 + (k - 256)];
        ws[idx] = __float2half_rn(v);
    } else if (b < NB_WS + NB_WO) {
        int idx = (b - NB_WS) * 256 + tid;
        int rr = idx / 416, k = idx % 416;
        int old = (rr & 3) * 256 + (rr >> 2);
        float v = (k < 400) ? W_ih[(size_t)old * 432 + k] : 0.f;
        wo[idx] = __float2half_rn(v);
    } else if (b == NB_WS + NB_WO) {
        for (int idx = tid; idx < 4608; idx += 256) {
            int cidx = idx >> 8;
            int koff = cidx >> 1, cih = cidx & 1;
            int rem = idx & 255;
            int co = rem >> 4, ci = rem & 15;
            float v = c2w[(co * 32 + cih * 16 + ci) * 9 + koff];
            uint32_t off = cidx * 512 + swz32(co, ci >> 3) + (ci & 7) * 2;
            *(__half*)(w2pack + off) = __float2half_rn(v);
        }
    } else {
        int t = (b - NB_WS - NB_WO - 1) * 256 + tid;
        int i = t >> 4, k = t & 15;
        int d = i * 32 + k;
        const size_t seg = (size_t)BATCH * 32;
        sp[d]           = __float2half_rn(pid_emb[pid[i] * 16 + k]);
        sp[seg + d]     = __float2half_rn(sid_emb[sid[i] * 16 + k]);
        sp[2 * seg + d] = __float2half_rn(sid_emb[sid0[i] * 16 + k]);
        sp[3 * seg + d] = __float2half_rn(sid_emb[sid1[i] * 16 + k]);
    }
}

// ================= encoder: R13 version (fp16, 2 images/block, double-buffered) ===========
#define E_IMGA  0
#define E_IMGB  16384
#define E_C1    32768
#define E_W2    98304
#define E_ZERO  107520
#define ENC_SMEM_BYTES 107584

__global__ void __launch_bounds__(512, 2) encoder_kernel(
                               const float* __restrict__ obs,
                               const float* __restrict__ c1w, const float* __restrict__ c1b,
                               const float* __restrict__ c2b,
                               const uint8_t* __restrict__ w2pack,
                               __half* __restrict__ obs_emb)
{
    extern __shared__ __align__(16) char smem[];
    uint32_t sb = smem_to_u32(smem);
    int tid = threadIdx.x;
    int lane = tid & 31, w = tid >> 5;
    int img0 = blockIdx.x * 2;

    for (int i = tid; i < 576; i += 512) CP16(sb + E_W2 + i * 16, w2pack + i * 16);
    {
        const uint8_t* src = (const uint8_t*)(obs + (size_t)img0 * 4096);
        for (int i = tid; i < 1024; i += 512) CP16(sb + E_IMGA + i * 16, src + i * 16);
    }
    CP_COMMIT();
    if (tid < 4) ((uint4*)(smem + E_ZERO))[tid] = make_uint4(0, 0, 0, 0);

    int g = lane >> 2, cq = lane & 3;
    int k0c = 2 * cq, k1c = 2 * cq + 1;
    int ky0 = k0c / 3, kx0 = k0c % 3;
    int ky1 = k1c / 3, kx1 = k1c % 3;
    uint32_t b1[4][2];
    #pragma unroll
    for (int j = 0; j < 4; j++) {
        int n = j * 8 + g;
        b1[j][0] = pkh2(c1w[n * 9 + k0c], c1w[n * 9 + k1c]);
        b1[j][1] = pkh2((cq == 0) ? c1w[n * 9 + 8] : 0.f, 0.f);
    }
    float bia1a[4], bia1b[4];
    #pragma unroll
    for (int j = 0; j < 4; j++) {
        int cc = j * 8 + cq * 2;
        bia1a[j] = c1b[cc];
        bia1b[j] = c1b[cc + 1];
    }
    int p2 = w * 16 + (lane & 15);
    int oy2 = p2 >> 4, ox2 = p2 & 15;
    int khalf = lane >> 4;
    int nrow = (lane & 7) + ((lane >> 4) << 3);
    uint32_t chB = (lane >> 3) & 1;
    uint32_t boff = swz32(nrow, chB);
    uint32_t zbase = sb + (uint32_t)E_ZERO + (uint32_t)khalf * 16u;

    for (int it = 0; it < 2; it++) {
        int img = img0 + it;
        float* s_img = (float*)(smem + (it ? E_IMGB : E_IMGA));
        CP_WAIT0();
        __syncthreads();

        #pragma unroll
        for (int t = 0; t < 4; t++) {
            int base = w * 64 + t * 16;
            int p0 = base + g, p1 = p0 + 8;
            int oy0 = p0 >> 5, ox0 = p0 & 31;
            int oy1 = p1 >> 5, ox1 = p1 & 31;
            int iy00 = 2 * oy0 - 1 + ky0, ix00 = 2 * ox0 - 1 + kx0;
            int iy01 = 2 * oy0 - 1 + ky1, ix01 = 2 * ox0 - 1 + kx1;
            int iy10 = 2 * oy1 - 1 + ky0, ix10 = 2 * ox1 - 1 + kx0;
            int iy11 = 2 * oy1 - 1 + ky1, ix11 = 2 * ox1 - 1 + kx1;
            float v00 = (iy00 >= 0 && ix00 >= 0) ? s_img[iy00 * 64 + ix00] : 0.f;
            float v01 = (iy01 >= 0 && ix01 >= 0) ? s_img[iy01 * 64 + ix01] : 0.f;
            float v10 = (iy10 >= 0 && ix10 >= 0) ? s_img[iy10 * 64 + ix10] : 0.f;
            float v11 = (iy11 >= 0 && ix11 >= 0) ? s_img[iy11 * 64 + ix11] : 0.f;
            float v08 = (cq == 0) ? s_img[(2 * oy0 + 1) * 64 + (2 * ox0 + 1)] : 0.f;
            float v18 = (cq == 0) ? s_img[(2 * oy1 + 1) * 64 + (2 * ox1 + 1)] : 0.f;
            uint32_t a[4];
            a[0] = pkh2(v00, v01);
            a[1] = pkh2(v10, v11);
            a[2] = pkh2(v08, 0.f);
            a[3] = pkh2(v18, 0.f);

            float acc[4][4];
            #pragma unroll
            for (int j = 0; j < 4; j++)
                #pragma unroll
                for (int q = 0; q < 4; q++) acc[j][q] = 0.f;
            #pragma unroll
            for (int j = 0; j < 4; j++) mma_f16(acc[j], a, b1[j]);

            #pragma unroll
            for (int j = 0; j < 4; j++) {
                #pragma unroll
                for (int rh = 0; rh < 2; rh++) {
                    int pos = base + g + rh * 8;
                    float v0 = fmaxf(acc[j][rh * 2 + 0] + bia1a[j], 0.f);
                    float v1 = fmaxf(acc[j][rh * 2 + 1] + bia1b[j], 0.f);
                    uint32_t addr = swz64((uint32_t)pos, (uint32_t)j) + cq * 4;
                    *(uint32_t*)(smem + E_C1 + addr) = pkh2(v0, v1);
                }
            }
        }
        __syncthreads();
        if (it == 0) {
            const uint8_t* src = (const uint8_t*)(obs + (size_t)(img0 + 1) * 4096);
            for (int i = tid; i < 1024; i += 512) CP16(sb + E_IMGB + i * 16, src + i * 16);
            CP_COMMIT();
        }

        float acc2[2][4];
        #pragma unroll
        for (int j = 0; j < 2; j++)
            #pragma unroll
            for (int q = 0; q < 4; q++) acc2[j][q] = 0.f;
        #pragma unroll
        for (int koff = 0; koff < 9; koff++) {
            const int ky = koff / 3, kx = koff % 3;
            int iy = 2 * oy2 - 1 + ky, ix = 2 * ox2 - 1 + kx;
            bool valid = (iy >= 0 && iy < 32 && ix >= 0 && ix < 32);
            int c1pos = iy * 32 + ix;
            uint32_t rbase = (uint32_t)c1pos * 64u;
            uint32_t rx = ((uint32_t)(c1pos >> 1) & 3u) << 4;
            #pragma unroll
            for (int cih = 0; cih < 2; cih++) {
                uint32_t chunkA = (uint32_t)(cih * 2 + khalf);
                uint32_t offA = rbase + ((chunkA << 4) ^ rx);
                uint32_t aA = valid ? (sb + E_C1 + offA) : zbase;
                uint32_t bb = sb + (uint32_t)(E_W2) + (uint32_t)(koff * 2 + cih) * 512u + boff;
                uint32_t a[4], bh[2][2];
                LDSM_X4(a[0], a[1], a[2], a[3], aA);
                LDSM_X4(bh[0][0], bh[0][1], bh[1][0], bh[1][1], bb);
                mma_f16(acc2[0], a, bh[0]);
                mma_f16(acc2[1], a, bh[1]);
            }
        }
        {
            float* s_c2 = (float*)(smem + (it ? E_IMGB : E_IMGA));
            #pragma unroll
            for (int j = 0; j < 2; j++) {
                int co = j * 8 + (lane & 3) * 2;
                float bia0 = c2b[co], bia1 = c2b[co + 1];
                #pragma unroll
                for (int rh = 0; rh < 2; rh++) {
                    int pos = w * 16 + (lane >> 2) + rh * 8;
                    float v0 = fmaxf(acc2[j][rh * 2 + 0] + bia0, 0.f);
                    float v1 = fmaxf(acc2[j][rh * 2 + 1] + bia1, 0.f);
                    *(float2*)(s_c2 + pos * 16 + co) = make_float2(v0, v1);
                }
            }
        }
        __syncthreads();
        {
            const float* s_c2 = (const float*)(smem + (it ? E_IMGB : E_IMGA));
            if (tid < 400) {
                int c = tid / 25; int r = tid % 25; int i = r / 5; int j = r % 5;
                float s = 0.f;
                #pragma unroll
                for (int dy = 0; dy < 3; dy++)
                    #pragma unroll
                    for (int dx = 0; dx < 3; dx++)
                        s += s_c2[((3 * i + dy) * 16 + (3 * j + dx)) * 16 + c];
                obs_emb[(size_t)img * 416 + tid] = __float2half_rn(s * (1.f / 9.f));
            }
        }
        __syncthreads();
    }
}

// ====== mma.sync fp16 GEMM; 3-stage cp.async pipeline; modes 0 raw / 1 lstm / 2 dual / 3 merged ==
#define SROW 80
#define GBUF (128 * SROW)
#define GSTAGE (2 * GBUF)
#define GEMM_SMEM_BYTES (3 * GSTAGE)

__global__ void __launch_bounds__(256, 2) gemm_mma_kernel(
    const __half* __restrict__ A1, int strideA, int KA,
    const __half* __restrict__ S1,
    const __half* __restrict__ W1, int strideB,
    int nchunks, int mode,
    const float* __restrict__ obs_part, const float* __restrict__ bias,
    const float* __restrict__ bias_b,
    const float* __restrict__ c_in,
    float* __restrict__ outD, float* __restrict__ c_out,
    __half* __restrict__ h_out)
{
    extern __shared__ __align__(16) char smc[];
    uint32_t sb = smem_to_u32(smc);

    int tid = threadIdx.x;
    int lane = tid & 31, wid = tid >> 5;
    int wm = wid & 3, wn = wid >> 2;
    int m0 = blockIdx.x * 128;
    int n0 = blockIdx.y * 128;

    int lrow = tid >> 1, lhalf = tid & 1;
    const __half* A_row = A1 + (size_t)(m0 + lrow) * strideA;
    const __half* S_row = S1 ? S1 + (size_t)(m0 + lrow) * 32 : nullptr;
    const __half* W_row = W1 + (size_t)(n0 + lrow) * strideB;

    float acc[2][8][4];
    #pragma unroll
    for (int i = 0; i < 2; i++)
        #pragma unroll
        for (int j = 0; j < 8; j++)
            #pragma unroll
            for (int r = 0; r < 4; r++) acc[i][j][r] = 0.f;

    uint32_t dstA = lrow * SROW + lhalf * 32;

    auto prefetch = [&](int c, int stage) {
        uint32_t sbase = sb + stage * GSTAGE;
        int col = c * 32 + lhalf * 16;
        const __half* pa = (col < KA) ? (A_row + col) : (S_row + (col - KA));
        uint32_t ad = sbase + dstA;
        CP16(ad, pa); CP16(ad + 16, pa + 8);
        const __half* pw = W_row + c * 32 + lhalf * 16;
        CP16(ad + GBUF, pw); CP16(ad + GBUF + 16, pw + 8);
        CP_COMMIT();
    };

    prefetch(0, 0);
    if (nchunks > 1) prefetch(1, 1);

    int stage = 0;
    for (int c = 0; c < nchunks; c++) {
        CP_WAIT1();
        __syncthreads();
        if (c + 2 < nchunks) {
            int ps = stage + 2; if (ps >= 3) ps -= 3;
            prefetch(c + 2, ps);
        }

        uint32_t sbase = sb + stage * GSTAGE;
        uint32_t baseA = sbase, baseB = sbase + GBUF;

        #pragma unroll
        for (int s = 0; s < 2; s++) {
            uint32_t a[2][4], b[8][2];
            int rA = wm * 32 + (lane & 15);
            int cA = s * 32 + ((lane >> 4) << 4);
            uint32_t adA0 = rA * SROW + cA;
            uint32_t adA1 = (rA + 16) * SROW + cA;
            int rB = wn * 64 + ((lane >> 4) << 3) + (lane & 7);
            int cB = s * 32 + (((lane >> 3) & 1) << 4);

            LDSM_X4(a[0][0], a[0][1], a[0][2], a[0][3], baseA + adA0);
            LDSM_X4(a[1][0], a[1][1], a[1][2], a[1][3], baseA + adA1);
            #pragma unroll
            for (int p = 0; p < 4; p++)
                LDSM_X4(b[2 * p][0], b[2 * p][1], b[2 * p + 1][0], b[2 * p + 1][1],
                        baseB + (rB + 16 * p) * SROW + cB);
            #pragma unroll
            for (int mi = 0; mi < 2; mi++)
                #pragma unroll
                for (int nj = 0; nj < 8; nj++) mma_f16(acc[mi][nj], a[mi], b[nj]);
        }
        if (++stage >= 3) stage = 0;
    }

    #pragma unroll
    for (int mi = 0; mi < 2; mi++) {
        #pragma unroll
        for (int nj = 0; nj < 8; nj++) {
            int colg = n0 + wn * 64 + 8 * nj + 2 * (lane & 3);
            #pragma unroll
            for (int rh = 0; rh < 2; rh++) {
                int row = m0 + wm * 32 + mi * 16 + (lane >> 2) + 8 * rh;
                float v0 = acc[mi][nj][rh * 2 + 0];
                float v1 = acc[mi][nj][rh * 2 + 1];
                if (mode == 0) {
                    float2* dst = (float2*)(outD + (size_t)row * 1024 + colg);
                    *dst = make_float2(v0, v1);
                } else {
                    float2 op = *(const float2*)(obs_part + (size_t)(row & (BATCH - 1)) * 1024 + colg);
                    v0 += op.x;
                    v1 += op.y;
                    float g0 = __shfl_xor_sync(0xffffffffu, v0, 1);
                    float g1 = __shfl_xor_sync(0xffffffffu, v1, 1);
                    if ((lane & 1) == 0) {
                        int unit = colg >> 2;
                        float cprev = c_in[(size_t)row * 256 + unit];
                        size_t d = (size_t)row * 256 + unit;
                        const float* bp = (mode == 3 && row >= BATCH) ? bias_b : bias;
                        float4 b4 = *(const float4*)(bp + colg);
                        {
                            float gi = v0 + b4.x, gf = v1 + b4.y, gg = g0 + b4.z, go = g1 + b4.w;
                            float si = 1.f / (1.f + __expf(-gi));
                            float sf = 1.f / (1.f + __expf(-gf));
                            float so = 1.f / (1.f + __expf(-go));
                            float c2 = sf * cprev + si * tanh_fast(gg);
                            float hv = so * tanh_fast(c2);
                            outD[d] = hv;
                            c_out[d] = c2;
                            h_out[d] = __float2half_rn(hv);
                        }
                        if (mode == 2) {
                            float4 b4b = *(const float4*)(bias_b + colg);
                            size_t d2 = d + (size_t)BATCH * 256;
                            float gi = v0 + b4b.x, gf = v1 + b4b.y, gg = g0 + b4b.z, go = g1 + b4b.w;
                            float si = 1.f / (1.f + __expf(-gi));
                            float sf = 1.f / (1.f + __expf(-gf));
                            float so = 1.f / (1.f + __expf(-go));
                            float c2 = sf * cprev + si * tanh_fast(gg);
                            float hv = so * tanh_fast(c2);
                            outD[d2] = hv;
                            c_out[d2] = c2;
                            h_out[d2] = __float2half_rn(hv);
                        }
                    }
                }
            }
        }
    }
}

// ================= step 0 =================
__global__ void step0_kernel(const float* __restrict__ op, const float* __restrict__ bias,
                             float* __restrict__ h, float* __restrict__ c,
                             __half* __restrict__ h_h)
{
    int idx = blockIdx.x * blockDim.x + threadIdx.x;
    if (idx >= BATCH * 256) return;
    int row = idx >> 8, u = idx & 255;
    float4 o4 = ((const float4*)(op + (size_t)row * 1024))[u];
    float4 b4 = ((const float4*)bias)[u];
    float gi = o4.x + b4.x, gg = o4.z + b4.z, go = o4.w + b4.w;
    float si = 1.f / (1.f + __expf(-gi));
    float so = 1.f / (1.f + __expf(-go));
    float c2 = si * tanh_fast(gg);
    float hv = so * tanh_fast(c2);
    h[idx] = hv;
    c[idx] = c2;
    h_h[idx] = __float2half_rn(hv);
}

// ================= mid-chain head (rp0 only) =================
__global__ void head_kernel(const float* __restrict__ h, const float* __restrict__ W,
                            const float* __restrict__ bvec,
                            const float* __restrict__ eps, float* __restrict__ out, int off,
                            float* __restrict__ rp_store)
{
    __shared__ float sW[4 * 256];
    __shared__ float sb[4];
    int tid = threadIdx.x;
    int lane = tid & 31, w = tid >> 5;
    for (int i = tid; i < 1024; i += 256) sW[i] = W[i];
    if (tid < 4) sb[tid] = bvec[tid];
    __syncthreads();

    int rowbase = blockIdx.x * 32 + w * 4;
    for (int rr = 0; rr < 4; rr++) {
        int row = rowbase + rr;
        const float* hp = h + (size_t)row * 256;
        float p0 = 0.f, p1 = 0.f, p2 = 0.f, p3 = 0.f;
        #pragma unroll
        for (int t = 0; t < 8; t++) {
            int k = lane + 32 * t;
            float hv = hp[k];
            p0 += hv * sW[k];
            p1 += hv * sW[256 + k];
            p2 += hv * sW[512 + k];
            p3 += hv * sW[768 + k];
        }
        #pragma unroll
        for (int o = 16; o; o >>= 1) {
            p0 += __shfl_xor_sync(0xffffffffu, p0, o);
            p1 += __shfl_xor_sync(0xffffffffu, p1, o);
            p2 += __shfl_xor_sync(0xffffffffu, p2, o);
            p3 += __shfl_xor_sync(0xffffffffu, p3, o);
        }
        if (lane == 0) {
            float v0 = p0 + sb[0], v1 = p1 + sb[1], v2 = p2 + sb[2], v3 = p3 + sb[3];
            float o0 = v0 + __expf(v2) * eps[row * 2 + 0];
            float o1 = v1 + __expf(v3) * eps[row * 2 + 1];
            out[(size_t)row * 15 + off + 0] = o0;
            out[(size_t)row * 15 + off + 1] = o1;
            rp_store[row * 2 + 0] = o0;
            rp_store[row * 2 + 1] = o1;
        }
    }
}

// ================= mega head: 6 heads in one kernel =================
__global__ void heads_kernel(const float* __restrict__ hb,
                             const float* __restrict__ pid_w, const float* __restrict__ pid_b,
                             const float* __restrict__ sid_w, const float* __restrict__ sid_b,
                             const float* __restrict__ rp_w, const float* __restrict__ rp_b,
                             const float* __restrict__ eps_rp, const float* __restrict__ eps_rp1,
                             float* __restrict__ out)
{
    __shared__ float sW[2304];
    __shared__ float sB[12];
    int tid = threadIdx.x;
    int lane = tid & 31, w = tid >> 5;
    for (int i = tid; i < 768; i += 256) sW[i] = pid_w[i];
    for (int i = tid; i < 512; i += 256) sW[768 + i] = sid_w[i];
    for (int i = tid; i < 1024; i += 256) sW[1280 + i] = rp_w[i];
    if (tid < 3) sB[tid] = pid_b[tid];
    if (tid < 2) sB[4 + tid] = sid_b[tid];
    if (tid < 4) sB[8 + tid] = rp_b[tid];
    __syncthreads();

    const int Hidx[6] = {0, 1, 3, 2, 4, 6};
    const int Wof[6]  = {0, 768, 1280, 768, 768, 1280};
    const int Bof[6]  = {0, 4, 8, 4, 4, 8};
    const int Nout[6] = {3, 2, 4, 2, 2, 4};
    const int Off[6]  = {0, 3, 5, 7, 9, 13};

    int rowbase = blockIdx.x * 32 + w * 4;
    for (int rr = 0; rr < 4; rr++) {
        int row = rowbase + rr;
        #pragma unroll
        for (int e = 0; e < 6; e++) {
            const float* hp = hb + (size_t)Hidx[e] * BATCH * 256 + (size_t)row * 256;
            int wof = Wof[e];
            float p0 = 0.f, p1 = 0.f, p2 = 0.f, p3 = 0.f;
            #pragma unroll
            for (int t = 0; t < 8; t++) {
                int k = lane + 32 * t;
                float hv = hp[k];
                p0 += hv * sW[wof + k];
                p1 += hv * sW[wof + 256 + k];
                if (Nout[e] > 2) p2 += hv * sW[wof + 512 + k];
                if (Nout[e] > 3) p3 += hv * sW[wof + 768 + k];
            }
            #pragma unroll
            for (int o = 16; o; o >>= 1) {
                p0 += __shfl_xor_sync(0xffffffffu, p0, o);
                p1 += __shfl_xor_sync(0xffffffffu, p1, o);
                p2 += __shfl_xor_sync(0xffffffffu, p2, o);
                p3 += __shfl_xor_sync(0xffffffffu, p3, o);
            }
            if (lane == 0) {
                int off = Off[e];
                float b0 = sB[Bof[e]], b1 = sB[Bof[e] + 1];
                if (Nout[e] == 4) {
                    const float* ee = (e == 2) ? eps_rp : eps_rp1;
                    float v0 = p0 + b0, v1 = p1 + b1;
                    float v2 = p2 + sB[Bof[e] + 2], v3 = p3 + sB[Bof[e] + 3];
                    out[(size_t)row * 15 + off + 0] = v0 + __expf(v2) * ee[row * 2 + 0];
                    out[(size_t)row * 15 + off + 1] = v1 + __expf(v3) * ee[row * 2 + 1];
                } else {
                    out[(size_t)row * 15 + off + 0] = p0 + b0;
                    out[(size_t)row * 15 + off + 1] = p1 + b1;
                    if (Nout[e] > 2) out[(size_t)row * 15 + off + 2] = p2 + sB[Bof[e] + 2];
                }
            }
        }
    }
}

// ================= batched MLP =================
#define MLP_SMEM_FLOATS (200 + 104 + 100 * 101 + 104 + 16 * 101 + 16 + 2 * 32 * 104)
__global__ void mlp_kernel(const float* __restrict__ rp0,
                           const float* __restrict__ w1, const float* __restrict__ b1,
                           const float* __restrict__ w2, const float* __restrict__ b2,
                           const float* __restrict__ w3, const float* __restrict__ b3,
                           __half* __restrict__ emb)
{
    extern __shared__ float ms[];
    float* sw1 = ms;
    float* sb1 = sw1 + 200;
    float* sw2 = sb1 + 104;
    float* sb2 = sw2 + 100 * 101;
    float* sw3 = sb2 + 104;
    float* sb3 = sw3 + 16 * 101;
    float* z1  = sb3 + 16;
    float* z2  = z1 + 32 * 104;
    int tid = threadIdx.x;
    int r0 = blockIdx.x * 32;

    for (int i = tid; i < 200; i += 256) sw1[i] = w1[i];
    if (tid < 100) { sb1[tid] = b1[tid]; sb2[tid] = b2[tid]; }
    if (tid < 16) sb3[tid] = b3[tid];
    for (int i = tid; i < 10000; i += 256) { int u = i / 100, k = i - u * 100; sw2[u * 101 + k] = w2[i]; }
    for (int i = tid; i < 1600; i += 256) { int o = i / 100, k = i - o * 100; sw3[o * 101 + k] = w3[i]; }
    __syncthreads();

    for (int t = tid; t < 3200; t += 256) {
        int row = t / 100, u = t - row * 100;
        float x0 = rp0[(r0 + row) * 2], x1 = rp0[(r0 + row) * 2 + 1];
        z1[row * 104 + u] = tanh_fast(sb1[u] + sw1[u * 2] * x0 + sw1[u * 2 + 1] * x1);
    }
    __syncthreads();
    for (int t = tid; t < 3200; t += 256) {
        int row = t / 100, u = t - row * 100;
        float s = sb2[u];
        const float* wr = sw2 + u * 101;
        const float* zr = z1 + row * 104;
        #pragma unroll 4
        for (int k = 0; k < 100; k++) s += wr[k] * zr[k];
        z2[row * 104 + u] = tanh_fast(s);
    }
    __syncthreads();
    for (int t = tid; t < 512; t += 256) {
        int row = t >> 4, o = t & 15;
        float s = sb3[o];
        const float* wr = sw3 + o * 101;
        const float* zr = z2 + row * 104;
        #pragma unroll 4
        for (int k = 0; k < 100; k++) s += wr[k] * zr[k];
        emb[(size_t)(r0 + row) * 32 + o] = __float2half_rn(s);
    }
}

// ================= launch =================
extern "C" void kernel_launch(void* const* d_in, const int* in_sizes, int n_in,
                              void* d_out, int out_size)
{
    const float* obs        = (const float*)d_in[0];
    const int*   program_id = (const int*)d_in[1];
    const int*   shape_id   = (const int*)d_in[2];
    const int*   shape_id_0 = (const int*)d_in[3];
    const int*   shape_id_1 = (const int*)d_in[4];
    const float* eps_rp     = (const float*)d_in[5];
    const float* eps_rp0    = (const float*)d_in[6];
    const float* eps_rp1    = (const float*)d_in[7];
    const float* conv1_w    = (const float*)d_in[8];
    const float* conv1_b    = (const float*)d_in[9];
    const float* conv2_w    = (const float*)d_in[10];
    const float* conv2_b    = (const float*)d_in[11];
    const float* mlp_w1     = (const float*)d_in[12];
    const float* mlp_b1     = (const float*)d_in[13];
    const float* mlp_w2     = (const float*)d_in[14];
    const float* mlp_b2     = (const float*)d_in[15];
    const float* mlp_w3     = (const float*)d_in[16];
    const float* mlp_b3     = (const float*)d_in[17];
    const float* W_ih       = (const float*)d_in[18];
    const float* b_ih       = (const float*)d_in[19];
    const float* W_hh       = (const float*)d_in[20];
    const float* b_hh       = (const float*)d_in[21];
    const float* addr_emb   = (const float*)d_in[22];
    const float* pid_emb    = (const float*)d_in[23];
    const float* sid_emb    = (const float*)d_in[24];
    const float* pid_ext_w  = (const float*)d_in[25];
    const float* pid_ext_b  = (const float*)d_in[26];
    const float* sid_ext_w  = (const float*)d_in[27];
    const float* sid_ext_b  = (const float*)d_in[28];
    const float* rp_ext_w   = (const float*)d_in[29];
    const float* rp_ext_b   = (const float*)d_in[30];
    float* out = (float*)d_out;

    float *obs_part, *bias, *rp0, *hb, *cb;
    __half *ws, *wo, *oe, *hh, *sp;
    uint8_t* w2p;
    cudaGetSymbolAddress((void**)&obs_part, g_obs_part);
    cudaGetSymbolAddress((void**)&bias,     g_bias);
    cudaGetSymbolAddress((void**)&rp0,      g_rp0);
    cudaGetSymbolAddress((void**)&hb,       g_hbuf);
    cudaGetSymbolAddress((void**)&cb,       g_cbuf);
    cudaGetSymbolAddress((void**)&ws,       g_Ws);
    cudaGetSymbolAddress((void**)&wo,       g_Wo);
    cudaGetSymbolAddress((void**)&oe,       g_obsE);
    cudaGetSymbolAddress((void**)&hh,       g_hh);
    cudaGetSymbolAddress((void**)&sp,       g_samp);
    cudaGetSymbolAddress((void**)&w2p,      g_w2pack);
    #define HBUF(i) (hb + (size_t)(i) * BATCH * HID)
    #define CBUF(i) (cb + (size_t)(i) * BATCH * HID)
    #define HH(i)   (hh + (size_t)(i) * BATCH * HID)
    #define SP(i)   (sp + (size_t)(i) * BATCH * 32)

    cudaFuncSetAttribute(encoder_kernel, cudaFuncAttributeMaxDynamicSharedMemorySize, ENC_SMEM_BYTES);
    cudaFuncSetAttribute(gemm_mma_kernel, cudaFuncAttributeMaxDynamicSharedMemorySize, GEMM_SMEM_BYTES);
    cudaFuncSetAttribute(mlp_kernel, cudaFuncAttributeMaxDynamicSharedMemorySize, MLP_SMEM_FLOATS * 4);

    // launch order: obs GEMM is 4th -> profiled
    bias_kernel<<<7, 1024>>>(b_ih, b_hh, addr_emb, W_ih, bias);
    prep_all_kernel<<<NB_WS + NB_WO + 1 + NB_GA, 256>>>(W_hh, W_ih, conv2_w,
                                                        program_id, shape_id, shape_id_0, shape_id_1,
                                                        pid_emb, sid_emb, ws, wo, w2p, sp);
    encoder_kernel<<<BATCH / 2, 512, ENC_SMEM_BYTES>>>(obs, conv1_w, conv1_b, conv2_b, w2p, oe);

    dim3 ggrid(BATCH / 128, 8);
    // obs_part (mode 0)
    gemm_mma_kernel<<<ggrid, 256, GEMM_SMEM_BYTES>>>(oe, 416, 416, nullptr, wo, 416, 13, 0,
                                    nullptr, nullptr, nullptr, nullptr, obs_part, nullptr, nullptr);
    // h0,c0
    step0_kernel<<<(BATCH * 256 + 255) / 256, 256>>>(obs_part, bias, HBUF(0), CBUF(0), HH(0));
    // G12: dual-bias (aid1 -> idx1 h1, aid2 -> idx2 h1b), A=h0, samp=pid
    gemm_mma_kernel<<<ggrid, 256, GEMM_SMEM_BYTES>>>(HH(0), 256, 256, SP(0), ws, 288, 9, 2,
                                    obs_part, bias + 1 * 1024, bias + 2 * 1024, CBUF(0),
                                    HBUF(1), CBUF(1), HH(1));
    // G34: merged M=8192; A=[h1;h1b], samp=[sid;sid0], bias aid4 / aid3 -> [h2;h2b]
    {
        dim3 mg(2 * BATCH / 128, 8);
        gemm_mma_kernel<<<mg, 256, GEMM_SMEM_BYTES>>>(HH(1), 256, 256, SP(1), ws, 288, 9, 3,
                                    obs_part, bias + 4 * 1024, bias + 3 * 1024, CBUF(1),
                                    HBUF(3), CBUF(3), HH(3));
    }
    // step5: h3b = step(sid1, aid5, h2b=idx4) -> idx5
    gemm_mma_kernel<<<ggrid, 256, GEMM_SMEM_BYTES>>>(HH(4), 256, 256, SP(3), ws, 288, 9, 1,
                                    obs_part, bias + 5 * 1024, nullptr, CBUF(4),
                                    HBUF(5), CBUF(5), HH(5));
    // rp0 head (critical)
    head_kernel<<<128, 256>>>(HBUF(5), rp_ext_w, rp_ext_b, eps_rp0, out, 11, rp0);
    mlp_kernel<<<128, 256, MLP_SMEM_FLOATS * 4>>>(rp0, mlp_w1, mlp_b1, mlp_w2, mlp_b2,
                                                  mlp_w3, mlp_b3, SP(4));
    // step6: h4b = step(rp0emb, aid6, h3b=idx5) -> idx6
    gemm_mma_kernel<<<ggrid, 256, GEMM_SMEM_BYTES>>>(HH(5), 256, 256, SP(4), ws, 288, 9, 1,
                                    obs_part, bias + 6 * 1024, nullptr, CBUF(5),
                                    HBUF(6), CBUF(6), HH(6));
    // all remaining heads
    heads_kernel<<<128, 256>>>(hb, pid_ext_w, pid_ext_b, sid_ext_w, sid_ext_b,
                               rp_ext_w, rp_ext_b, eps_rp, eps_rp1, out);
}

// round 15
// speedup vs baseline: 1.0747x; 1.0196x over previous
#include <cuda_runtime.h>
#include <cuda_fp16.h>
#include <math.h>
#include <stdint.h>

#define BATCH 4096
#define HID 256

// ================= scratch (static device memory; zero-initialized) ==========
__device__ float g_obs_part[BATCH * 1024];
__device__ float g_bias[7 * 1024];
__device__ float g_hbuf[7][BATCH * HID];
__device__ float g_cbuf[7][BATCH * HID];
__device__ __half g_obsE[BATCH * 416];
__device__ __half g_hh[7][BATCH * 256];
__device__ __half g_samp[5][BATCH * 32];
__device__ __half g_Ws[1024 * 288];
__device__ __half g_Wo[1024 * 416];
__device__ __align__(16) uint8_t g_w2pack[9216];

__device__ __forceinline__ uint32_t smem_to_u32(const void* p) {
    uint32_t a;
    asm("{ .reg .u64 t; cvta.to.shared.u64 t, %1; cvt.u32.u64 %0, t; }" : "=r"(a) : "l"(p));
    return a;
}

#define LDSM_X4(r0, r1, r2, r3, addr) \
    asm volatile("ldmatrix.sync.aligned.m8n8.x4.shared.b16 {%0,%1,%2,%3}, [%4];" \
                 : "=r"(r0), "=r"(r1), "=r"(r2), "=r"(r3) : "r"(addr))

#define CP16(dst, src) \
    asm volatile("cp.async.cg.shared.global [%0], [%1], 16;" :: "r"(dst), "l"(src))
#define CP_COMMIT() asm volatile("cp.async.commit_group;")
#define CP_WAIT0()  asm volatile("cp.async.wait_group 0;")
#define CP_WAIT1()  asm volatile("cp.async.wait_group 1;")

__device__ __forceinline__ void mma_f16(float* d, const uint32_t* a, const uint32_t* b) {
    asm volatile("mma.sync.aligned.m16n8k16.row.col.f32.f16.f16.f32 "
                 "{%0,%1,%2,%3}, {%4,%5,%6,%7}, {%8,%9}, {%0,%1,%2,%3};"
                 : "+f"(d[0]), "+f"(d[1]), "+f"(d[2]), "+f"(d[3])
                 : "r"(a[0]), "r"(a[1]), "r"(a[2]), "r"(a[3]), "r"(b[0]), "r"(b[1]));
}

__device__ __forceinline__ float tanh_fast(float x) {
    float e = __expf(2.f * x);
    return 1.f - __fdividef(2.f, e + 1.f);
}

__device__ __forceinline__ uint32_t pkh2(float a, float b) {
    __half2 h2 = __floats2half2_rn(a, b);
    return *reinterpret_cast<uint32_t*>(&h2);
}

__device__ __forceinline__ uint32_t swz32(uint32_t row, uint32_t chunk) {
    return row * 32u + ((chunk ^ ((row >> 2) & 1u)) << 4);
}
__device__ __forceinline__ uint32_t swz64(uint32_t row, uint32_t chunk) {
    return row * 64u + ((chunk ^ ((row >> 1) & 3u)) << 4);
}

__global__ void bias_kernel(const float* __restrict__ b_ih, const float* __restrict__ b_hh,
                            const float* __restrict__ addr_emb, const float* __restrict__ W_ih,
                            float* __restrict__ bias)
{
    int aid = blockIdx.x;
    int r = threadIdx.x;
    float s = b_ih[r] + b_hh[r];
    #pragma unroll
    for (int k = 0; k < 16; k++)
        s += addr_emb[aid * 16 + k] * W_ih[(size_t)r * 432 + 416 + k];
    int g = r >> 8, u = r & 255;
    bias[aid * 1024 + u * 4 + g] = s;
}

// ================= prep part 1: ws =================
#define NB_WS 1152
__global__ void prep_ws_kernel(const float* __restrict__ W_hh, const float* __restrict__ W_ih,
                               __half* __restrict__ ws)
{
    int idx = blockIdx.x * 256 + threadIdx.x;
    int rr = idx / 288, k = idx % 288;
    int old = (rr & 3) * 256 + (rr >> 2);
    float v = 0.f;
    if (k < 256) v = W_hh[(size_t)old * 256 + k];
    else if (k < 272) v = W_ih[(size_t)old * 432 + 400 + (k - 256)];
    ws[idx] = __float2half_rn(v);
}

// ================= prep part 2: wo + w2pack + gather =================
#define NB_WO 1664
#define NB_GA 256
__global__ void prep_rest_kernel(const float* __restrict__ W_ih, const float* __restrict__ c2w,
                                 const int* __restrict__ pid, const int* __restrict__ sid,
                                 const int* __restrict__ sid0, const int* __restrict__ sid1,
                                 const float* __restrict__ pid_emb, const float* __restrict__ sid_emb,
                                 __half* __restrict__ wo, uint8_t* __restrict__ w2pack,
                                 __half* __restrict__ sp)
{
    int b = blockIdx.x;
    int tid = threadIdx.x;
    if (b < NB_WO) {
        int idx = b * 256 + tid;
        int rr = idx / 416, k = idx % 416;
        int old = (rr & 3) * 256 + (rr >> 2);
        float v = (k < 400) ? W_ih[(size_t)old * 432 + k] : 0.f;
        wo[idx] = __float2half_rn(v);
    } else if (b == NB_WO) {
        for (int idx = tid; idx < 4608; idx += 256) {
            int cidx = idx >> 8;
            int koff = cidx >> 1, cih = cidx & 1;
            int rem = idx & 255;
            int co = rem >> 4, ci = rem & 15;
            float v = c2w[(co * 32 + cih * 16 + ci) * 9 + koff];
            uint32_t off = cidx * 512 + swz32(co, ci >> 3) + (ci & 7) * 2;
            *(__half*)(w2pack + off) = __float2half_rn(v);
        }
    } else {
        int t = (b - NB_WO - 1) * 256 + tid;
        int i = t >> 4, k = t & 15;
        int d = i * 32 + k;
        const size_t seg = (size_t)BATCH * 32;
        sp[d]           = __float2half_rn(pid_emb[pid[i] * 16 + k]);
        sp[seg + d]     = __float2half_rn(sid_emb[sid[i] * 16 + k]);
        sp[2 * seg + d] = __float2half_rn(sid_emb[sid0[i] * 16 + k]);
        sp[3 * seg + d] = __float2half_rn(sid_emb[sid1[i] * 16 + k]);
    }
}

// ================= encoder: fp16, 4 images/block, double-buffered img ===========
#define E_IMGA  0
#define E_IMGB  16384
#define E_C1    32768
#define E_W2    98304
#define E_ZERO  107520
#define ENC_SMEM_BYTES 107584

__global__ void __launch_bounds__(512, 2) encoder_kernel(
                               const float* __restrict__ obs,
                               const float* __restrict__ c1w, const float* __restrict__ c1b,
                               const float* __restrict__ c2b,
                               const uint8_t* __restrict__ w2pack,
                               __half* __restrict__ obs_emb)
{
    extern __shared__ __align__(16) char smem[];
    uint32_t sb = smem_to_u32(smem);
    int tid = threadIdx.x;
    int lane = tid & 31, w = tid >> 5;
    int img0 = blockIdx.x * 4;

    for (int i = tid; i < 576; i += 512) CP16(sb + E_W2 + i * 16, w2pack + i * 16);
    {
        const uint8_t* src = (const uint8_t*)(obs + (size_t)img0 * 4096);
        for (int i = tid; i < 1024; i += 512) CP16(sb + E_IMGA + i * 16, src + i * 16);
    }
    CP_COMMIT();
    if (tid < 4) ((uint4*)(smem + E_ZERO))[tid] = make_uint4(0, 0, 0, 0);

    int g = lane >> 2, cq = lane & 3;
    int k0c = 2 * cq, k1c = 2 * cq + 1;
    int ky0 = k0c / 3, kx0 = k0c % 3;
    int ky1 = k1c / 3, kx1 = k1c % 3;
    uint32_t b1[4][2];
    #pragma unroll
    for (int j = 0; j < 4; j++) {
        int n = j * 8 + g;
        b1[j][0] = pkh2(c1w[n * 9 + k0c], c1w[n * 9 + k1c]);
        b1[j][1] = pkh2((cq == 0) ? c1w[n * 9 + 8] : 0.f, 0.f);
    }
    float bia1a[4], bia1b[4];
    #pragma unroll
    for (int j = 0; j < 4; j++) {
        int cc = j * 8 + cq * 2;
        bia1a[j] = c1b[cc];
        bia1b[j] = c1b[cc + 1];
    }
    int p2 = w * 16 + (lane & 15);
    int oy2 = p2 >> 4, ox2 = p2 & 15;
    int khalf = lane >> 4;
    int nrow = (lane & 7) + ((lane >> 4) << 3);
    uint32_t chB = (lane >> 3) & 1;
    uint32_t boff = swz32(nrow, chB);
    uint32_t zbase = sb + (uint32_t)E_ZERO + (uint32_t)khalf * 16u;

    for (int it = 0; it < 4; it++) {
        int img = img0 + it;
        uint32_t curbuf = (it & 1) ? E_IMGB : E_IMGA;
        float* s_img = (float*)(smem + curbuf);
        CP_WAIT0();
        __syncthreads();

        #pragma unroll
        for (int t = 0; t < 4; t++) {
            int base = w * 64 + t * 16;
            int p0 = base + g, p1 = p0 + 8;
            int oy0 = p0 >> 5, ox0 = p0 & 31;
            int oy1 = p1 >> 5, ox1 = p1 & 31;
            int iy00 = 2 * oy0 - 1 + ky0, ix00 = 2 * ox0 - 1 + kx0;
            int iy01 = 2 * oy0 - 1 + ky1, ix01 = 2 * ox0 - 1 + kx1;
            int iy10 = 2 * oy1 - 1 + ky0, ix10 = 2 * ox1 - 1 + kx0;
            int iy11 = 2 * oy1 - 1 + ky1, ix11 = 2 * ox1 - 1 + kx1;
            float v00 = (iy00 >= 0 && ix00 >= 0) ? s_img[iy00 * 64 + ix00] : 0.f;
            float v01 = (iy01 >= 0 && ix01 >= 0) ? s_img[iy01 * 64 + ix01] : 0.f;
            float v10 = (iy10 >= 0 && ix10 >= 0) ? s_img[iy10 * 64 + ix10] : 0.f;
            float v11 = (iy11 >= 0 && ix11 >= 0) ? s_img[iy11 * 64 + ix11] : 0.f;
            float v08 = (cq == 0) ? s_img[(2 * oy0 + 1) * 64 + (2 * ox0 + 1)] : 0.f;
            float v18 = (cq == 0) ? s_img[(2 * oy1 + 1) * 64 + (2 * ox1 + 1)] : 0.f;
            uint32_t a[4];
            a[0] = pkh2(v00, v01);
            a[1] = pkh2(v10, v11);
            a[2] = pkh2(v08, 0.f);
            a[3] = pkh2(v18, 0.f);

            float acc[4][4];
            #pragma unroll
            for (int j = 0; j < 4; j++)
                #pragma unroll
                for (int q = 0; q < 4; q++) acc[j][q] = 0.f;
            #pragma unroll
            for (int j = 0; j < 4; j++) mma_f16(acc[j], a, b1[j]);

            #pragma unroll
            for (int j = 0; j < 4; j++) {
                #pragma unroll
                for (int rh = 0; rh < 2; rh++) {
                    int pos = base + g + rh * 8;
                    float v0 = fmaxf(acc[j][rh * 2 + 0] + bia1a[j], 0.f);
                    float v1 = fmaxf(acc[j][rh * 2 + 1] + bia1b[j], 0.f);
                    uint32_t addr = swz64((uint32_t)pos, (uint32_t)j) + cq * 4;
                    *(uint32_t*)(smem + E_C1 + addr) = pkh2(v0, v1);
                }
            }
        }
        __syncthreads();
        if (it < 3) {
            uint32_t nxtbuf = ((it + 1) & 1) ? E_IMGB : E_IMGA;
            const uint8_t* src = (const uint8_t*)(obs + (size_t)(img + 1) * 4096);
            for (int i = tid; i < 1024; i += 512) CP16(sb + nxtbuf + i * 16, src + i * 16);
            CP_COMMIT();
        }

        float acc2[2][4];
        #pragma unroll
        for (int j = 0; j < 2; j++)
            #pragma unroll
            for (int q = 0; q < 4; q++) acc2[j][q] = 0.f;
        #pragma unroll
        for (int koff = 0; koff < 9; koff++) {
            const int ky = koff / 3, kx = koff % 3;
            int iy = 2 * oy2 - 1 + ky, ix = 2 * ox2 - 1 + kx;
            bool valid = (iy >= 0 && iy < 32 && ix >= 0 && ix < 32);
            int c1pos = iy * 32 + ix;
            uint32_t rbase = (uint32_t)c1pos * 64u;
            uint32_t rx = ((uint32_t)(c1pos >> 1) & 3u) << 4;
            #pragma unroll
            for (int cih = 0; cih < 2; cih++) {
                uint32_t chunkA = (uint32_t)(cih * 2 + khalf);
                uint32_t offA = rbase + ((chunkA << 4) ^ rx);
                uint32_t aA = valid ? (sb + E_C1 + offA) : zbase;
                uint32_t bb = sb + (uint32_t)(E_W2) + (uint32_t)(koff * 2 + cih) * 512u + boff;
                uint32_t a[4], bh[2][2];
                LDSM_X4(a[0], a[1], a[2], a[3], aA);
                LDSM_X4(bh[0][0], bh[0][1], bh[1][0], bh[1][1], bb);
                mma_f16(acc2[0], a, bh[0]);
                mma_f16(acc2[1], a, bh[1]);
            }
        }
        {
            float* s_c2 = (float*)(smem + curbuf);
            #pragma unroll
            for (int j = 0; j < 2; j++) {
                int co = j * 8 + (lane & 3) * 2;
                float bia0 = c2b[co], bia1 = c2b[co + 1];
                #pragma unroll
                for (int rh = 0; rh < 2; rh++) {
                    int pos = w * 16 + (lane >> 2) + rh * 8;
                    float v0 = fmaxf(acc2[j][rh * 2 + 0] + bia0, 0.f);
                    float v1 = fmaxf(acc2[j][rh * 2 + 1] + bia1, 0.f);
                    *(float2*)(s_c2 + pos * 16 + co) = make_float2(v0, v1);
                }
            }
        }
        __syncthreads();
        {
            const float* s_c2 = (const float*)(smem + curbuf);
            if (tid < 400) {
                int c = tid / 25; int r = tid % 25; int i = r / 5; int j = r % 5;
                float s = 0.f;
                #pragma unroll
                for (int dy = 0; dy < 3; dy++)
                    #pragma unroll
                    for (int dx = 0; dx < 3; dx++)
                        s += s_c2[((3 * i + dy) * 16 + (3 * j + dx)) * 16 + c];
                obs_emb[(size_t)img * 416 + tid] = __float2half_rn(s * (1.f / 9.f));
            }
        }
        __syncthreads();
    }
}

// ====== mma.sync fp16 GEMM; 3-stage cp.async pipeline; modes 0 raw / 1 lstm / 2 dual / 3 merged ==
#define SROW 80
#define GBUF (128 * SROW)
#define GSTAGE (2 * GBUF)
#define GEMM_SMEM_BYTES (3 * GSTAGE)

__global__ void __launch_bounds__(256, 2) gemm_mma_kernel(
    const __half* __restrict__ A1, int strideA, int KA,
    const __half* __restrict__ S1,
    const __half* __restrict__ W1, int strideB,
    int nchunks, int mode,
    const float* __restrict__ obs_part, const float* __restrict__ bias,
    const float* __restrict__ bias_b,
    const float* __restrict__ c_in,
    float* __restrict__ outD, float* __restrict__ c_out,
    __half* __restrict__ h_out)
{
    extern __shared__ __align__(16) char smc[];
    uint32_t sb = smem_to_u32(smc);

    int tid = threadIdx.x;
    int lane = tid & 31, wid = tid >> 5;
    int wm = wid & 3, wn = wid >> 2;
    int m0 = blockIdx.x * 128;
    int n0 = blockIdx.y * 128;

    int lrow = tid >> 1, lhalf = tid & 1;
    const __half* A_row = A1 + (size_t)(m0 + lrow) * strideA;
    const __half* S_row = S1 ? S1 + (size_t)(m0 + lrow) * 32 : nullptr;
    const __half* W_row = W1 + (size_t)(n0 + lrow) * strideB;

    float acc[2][8][4];
    #pragma unroll
    for (int i = 0; i < 2; i++)
        #pragma unroll
        for (int j = 0; j < 8; j++)
            #pragma unroll
            for (int r = 0; r < 4; r++) acc[i][j][r] = 0.f;

    uint32_t dstA = lrow * SROW + lhalf * 32;

    auto prefetch = [&](int c, int stage) {
        uint32_t sbase = sb + stage * GSTAGE;
        int col = c * 32 + lhalf * 16;
        const __half* pa = (col < KA) ? (A_row + col) : (S_row + (col - KA));
        uint32_t ad = sbase + dstA;
        CP16(ad, pa); CP16(ad + 16, pa + 8);
        const __half* pw = W_row + c * 32 + lhalf * 16;
        CP16(ad + GBUF, pw); CP16(ad + GBUF + 16, pw + 8);
        CP_COMMIT();
    };

    prefetch(0, 0);
    if (nchunks > 1) prefetch(1, 1);

    int stage = 0;
    for (int c = 0; c < nchunks; c++) {
        CP_WAIT1();
        __syncthreads();
        if (c + 2 < nchunks) {
            int ps = stage + 2; if (ps >= 3) ps -= 3;
            prefetch(c + 2, ps);
        }

        uint32_t sbase = sb + stage * GSTAGE;
        uint32_t baseA = sbase, baseB = sbase + GBUF;

        #pragma unroll
        for (int s = 0; s < 2; s++) {
            uint32_t a[2][4], b[8][2];
            int rA = wm * 32 + (lane & 15);
            int cA = s * 32 + ((lane >> 4) << 4);
            uint32_t adA0 = rA * SROW + cA;
            uint32_t adA1 = (rA + 16) * SROW + cA;
            int rB = wn * 64 + ((lane >> 4) << 3) + (lane & 7);
            int cB = s * 32 + (((lane >> 3) & 1) << 4);

            LDSM_X4(a[0][0], a[0][1], a[0][2], a[0][3], baseA + adA0);
            LDSM_X4(a[1][0], a[1][1], a[1][2], a[1][3], baseA + adA1);
            #pragma unroll
            for (int p = 0; p < 4; p++)
                LDSM_X4(b[2 * p][0], b[2 * p][1], b[2 * p + 1][0], b[2 * p + 1][1],
                        baseB + (rB + 16 * p) * SROW + cB);
            #pragma unroll
            for (int mi = 0; mi < 2; mi++)
                #pragma unroll
                for (int nj = 0; nj < 8; nj++) mma_f16(acc[mi][nj], a[mi], b[nj]);
        }
        if (++stage >= 3) stage = 0;
    }

    #pragma unroll
    for (int mi = 0; mi < 2; mi++) {
        #pragma unroll
        for (int nj = 0; nj < 8; nj++) {
            int colg = n0 + wn * 64 + 8 * nj + 2 * (lane & 3);
            #pragma unroll
            for (int rh = 0; rh < 2; rh++) {
                int row = m0 + wm * 32 + mi * 16 + (lane >> 2) + 8 * rh;
                float v0 = acc[mi][nj][rh * 2 + 0];
                float v1 = acc[mi][nj][rh * 2 + 1];
                if (mode == 0) {
                    float2* dst = (float2*)(outD + (size_t)row * 1024 + colg);
                    *dst = make_float2(v0, v1);
                } else {
                    float2 op = *(const float2*)(obs_part + (size_t)(row & (BATCH - 1)) * 1024 + colg);
                    v0 += op.x;
                    v1 += op.y;
                    float g0 = __shfl_xor_sync(0xffffffffu, v0, 1);
                    float g1 = __shfl_xor_sync(0xffffffffu, v1, 1);
                    if ((lane & 1) == 0) {
                        int unit = colg >> 2;
                        float cprev = c_in[(size_t)row * 256 + unit];
                        size_t d = (size_t)row * 256 + unit;
                        const float* bp = (mode == 3 && row >= BATCH) ? bias_b : bias;
                        float4 b4 = *(const float4*)(bp + colg);
                        {
                            float gi = v0 + b4.x, gf = v1 + b4.y, gg = g0 + b4.z, go = g1 + b4.w;
                            float si = 1.f / (1.f + __expf(-gi));
                            float sf = 1.f / (1.f + __expf(-gf));
                            float so = 1.f / (1.f + __expf(-go));
                            float c2 = sf * cprev + si * tanh_fast(gg);
                            float hv = so * tanh_fast(c2);
                            outD[d] = hv;
                            c_out[d] = c2;
                            h_out[d] = __float2half_rn(hv);
                        }
                        if (mode == 2) {
                            float4 b4b = *(const float4*)(bias_b + colg);
                            size_t d2 = d + (size_t)BATCH * 256;
                            float gi = v0 + b4b.x, gf = v1 + b4b.y, gg = g0 + b4b.z, go = g1 + b4b.w;
                            float si = 1.f / (1.f + __expf(-gi));
                            float sf = 1.f / (1.f + __expf(-gf));
                            float so = 1.f / (1.f + __expf(-go));
                            float c2 = sf * cprev + si * tanh_fast(gg);
                            float hv = so * tanh_fast(c2);
                            outD[d2] = hv;
                            c_out[d2] = c2;
                            h_out[d2] = __float2half_rn(hv);
                        }
                    }
                }
            }
        }
    }
}

// ================= step 0 =================
__global__ void step0_kernel(const float* __restrict__ op, const float* __restrict__ bias,
                             float* __restrict__ h, float* __restrict__ c,
                             __half* __restrict__ h_h)
{
    int idx = blockIdx.x * blockDim.x + threadIdx.x;
    if (idx >= BATCH * 256) return;
    int row = idx >> 8, u = idx & 255;
    float4 o4 = ((const float4*)(op + (size_t)row * 1024))[u];
    float4 b4 = ((const float4*)bias)[u];
    float gi = o4.x + b4.x, gg = o4.z + b4.z, go = o4.w + b4.w;
    float si = 1.f / (1.f + __expf(-gi));
    float so = 1.f / (1.f + __expf(-go));
    float c2 = si * tanh_fast(gg);
    float hv = so * tanh_fast(c2);
    h[idx] = hv;
    c[idx] = c2;
    h_h[idx] = __float2half_rn(hv);
}

// ================= fused rp0 head + MLP =================
#define HM_SMEM_FLOATS (1024 + 4 + 64 + 200 + 104 + 100 * 101 + 104 + 16 * 101 + 16 + 2 * 32 * 104)
__global__ void headmlp_kernel(const float* __restrict__ h, const float* __restrict__ W,
                               const float* __restrict__ bvec,
                               const float* __restrict__ eps, float* __restrict__ out,
                               const float* __restrict__ w1, const float* __restrict__ b1,
                               const float* __restrict__ w2, const float* __restrict__ b2,
                               const float* __restrict__ w3, const float* __restrict__ b3,
                               __half* __restrict__ emb)
{
    extern __shared__ float ms[];
    float* sWh = ms;                 // 1024
    float* sbh = sWh + 1024;         // 4
    float* srp = sbh + 4;            // 64
    float* sw1 = srp + 64;           // 200
    float* sb1 = sw1 + 200;          // 104
    float* sw2 = sb1 + 104;          // 100*101
    float* sb2 = sw2 + 100 * 101;    // 104
    float* sw3 = sb2 + 104;          // 16*101
    float* sb3 = sw3 + 16 * 101;     // 16
    float* z1  = sb3 + 16;           // 32*104
    float* z2  = z1 + 32 * 104;      // 32*104
    int tid = threadIdx.x;
    int lane = tid & 31, w = tid >> 5;
    int r0 = blockIdx.x * 32;

    for (int i = tid; i < 1024; i += 256) sWh[i] = W[i];
    if (tid < 4) sbh[tid] = bvec[tid];
    for (int i = tid; i < 200; i += 256) sw1[i] = w1[i];
    if (tid < 100) { sb1[tid] = b1[tid]; sb2[tid] = b2[tid]; }
    if (tid < 16) sb3[tid] = b3[tid];
    for (int i = tid; i < 10000; i += 256) { int u = i / 100, k = i - u * 100; sw2[u * 101 + k] = w2[i]; }
    for (int i = tid; i < 1600; i += 256) { int o = i / 100, k = i - o * 100; sw3[o * 101 + k] = w3[i]; }
    __syncthreads();

    // phase A: rp0 head (each warp: 4 rows)
    for (int rr = 0; rr < 4; rr++) {
        int lrow = w * 4 + rr;
        int row = r0 + lrow;
        const float* hp = h + (size_t)row * 256;
        float p0 = 0.f, p1 = 0.f, p2 = 0.f, p3 = 0.f;
        #pragma unroll
        for (int t = 0; t < 8; t++) {
            int k = lane + 32 * t;
            float hv = hp[k];
            p0 += hv * sWh[k];
            p1 += hv * sWh[256 + k];
            p2 += hv * sWh[512 + k];
            p3 += hv * sWh[768 + k];
        }
        #pragma unroll
        for (int o = 16; o; o >>= 1) {
            p0 += __shfl_xor_sync(0xffffffffu, p0, o);
            p1 += __shfl_xor_sync(0xffffffffu, p1, o);
            p2 += __shfl_xor_sync(0xffffffffu, p2, o);
            p3 += __shfl_xor_sync(0xffffffffu, p3, o);
        }
        if (lane == 0) {
            float v0 = p0 + sbh[0], v1 = p1 + sbh[1], v2 = p2 + sbh[2], v3 = p3 + sbh[3];
            float o0 = v0 + __expf(v2) * eps[row * 2 + 0];
            float o1 = v1 + __expf(v3) * eps[row * 2 + 1];
            out[(size_t)row * 15 + 11] = o0;
            out[(size_t)row * 15 + 12] = o1;
            srp[lrow * 2 + 0] = o0;
            srp[lrow * 2 + 1] = o1;
        }
    }
    __syncthreads();

    // phase B: MLP 2->100->100->16
    for (int t = tid; t < 3200; t += 256) {
        int row = t / 100, u = t - row * 100;
        float x0 = srp[row * 2], x1 = srp[row * 2 + 1];
        z1[row * 104 + u] = tanh_fast(sb1[u] + sw1[u * 2] * x0 + sw1[u * 2 + 1] * x1);
    }
    __syncthreads();
    for (int t = tid; t < 3200; t += 256) {
        int row = t / 100, u = t - row * 100;
        float s = sb2[u];
        const float* wr = sw2 + u * 101;
        const float* zr = z1 + row * 104;
        #pragma unroll 4
        for (int k = 0; k < 100; k++) s += wr[k] * zr[k];
        z2[row * 104 + u] = tanh_fast(s);
    }
    __syncthreads();
    for (int t = tid; t < 512; t += 256) {
        int row = t >> 4, o = t & 15;
        float s = sb3[o];
        const float* wr = sw3 + o * 101;
        const float* zr = z2 + row * 104;
        #pragma unroll 4
        for (int k = 0; k < 100; k++) s += wr[k] * zr[k];
        emb[(size_t)(r0 + row) * 32 + o] = __float2half_rn(s);
    }
}

// ================= mega head: 6 heads in one kernel =================
__global__ void heads_kernel(const float* __restrict__ hb,
                             const float* __restrict__ pid_w, const float* __restrict__ pid_b,
                             const float* __restrict__ sid_w, const float* __restrict__ sid_b,
                             const float* __restrict__ rp_w, const float* __restrict__ rp_b,
                             const float* __restrict__ eps_rp, const float* __restrict__ eps_rp1,
                             float* __restrict__ out)
{
    __shared__ float sW[2304];
    __shared__ float sB[12];
    int tid = threadIdx.x;
    int lane = tid & 31, w = tid >> 5;
    for (int i = tid; i < 768; i += 256) sW[i] = pid_w[i];
    for (int i = tid; i < 512; i += 256) sW[768 + i] = sid_w[i];
    for (int i = tid; i < 1024; i += 256) sW[1280 + i] = rp_w[i];
    if (tid < 3) sB[tid] = pid_b[tid];
    if (tid < 2) sB[4 + tid] = sid_b[tid];
    if (tid < 4) sB[8 + tid] = rp_b[tid];
    __syncthreads();

    const int Hidx[6] = {0, 1, 3, 2, 4, 6};
    const int Wof[6]  = {0, 768, 1280, 768, 768, 1280};
    const int Bof[6]  = {0, 4, 8, 4, 4, 8};
    const int Nout[6] = {3, 2, 4, 2, 2, 4};
    const int Off[6]  = {0, 3, 5, 7, 9, 13};

    int rowbase = blockIdx.x * 32 + w * 4;
    for (int rr = 0; rr < 4; rr++) {
        int row = rowbase + rr;
        #pragma unroll
        for (int e = 0; e < 6; e++) {
            const float* hp = hb + (size_t)Hidx[e] * BATCH * 256 + (size_t)row * 256;
            int wof = Wof[e];
            float p0 = 0.f, p1 = 0.f, p2 = 0.f, p3 = 0.f;
            #pragma unroll
            for (int t = 0; t < 8; t++) {
                int k = lane + 32 * t;
                float hv = hp[k];
                p0 += hv * sW[wof + k];
                p1 += hv * sW[wof + 256 + k];
                if (Nout[e] > 2) p2 += hv * sW[wof + 512 + k];
                if (Nout[e] > 3) p3 += hv * sW[wof + 768 + k];
            }
            #pragma unroll
            for (int o = 16; o; o >>= 1) {
                p0 += __shfl_xor_sync(0xffffffffu, p0, o);
                p1 += __shfl_xor_sync(0xffffffffu, p1, o);
                p2 += __shfl_xor_sync(0xffffffffu, p2, o);
                p3 += __shfl_xor_sync(0xffffffffu, p3, o);
            }
            if (lane == 0) {
                int off = Off[e];
                float b0 = sB[Bof[e]], b1 = sB[Bof[e] + 1];
                if (Nout[e] == 4) {
                    const float* ee = (e == 2) ? eps_rp : eps_rp1;
                    float v0 = p0 + b0, v1 = p1 + b1;
                    float v2 = p2 + sB[Bof[e] + 2], v3 = p3 + sB[Bof[e] + 3];
                    out[(size_t)row * 15 + off + 0] = v0 + __expf(v2) * ee[row * 2 + 0];
                    out[(size_t)row * 15 + off + 1] = v1 + __expf(v3) * ee[row * 2 + 1];
                } else {
                    out[(size_t)row * 15 + off + 0] = p0 + b0;
                    out[(size_t)row * 15 + off + 1] = p1 + b1;
                    if (Nout[e] > 2) out[(size_t)row * 15 + off + 2] = p2 + sB[Bof[e] + 2];
                }
            }
        }
    }
}

// ================= launch =================
extern "C" void kernel_launch(void* const* d_in, const int* in_sizes, int n_in,
                              void* d_out, int out_size)
{
    const float* obs        = (const float*)d_in[0];
    const int*   program_id = (const int*)d_in[1];
    const int*   shape_id   = (const int*)d_in[2];
    const int*   shape_id_0 = (const int*)d_in[3];
    const int*   shape_id_1 = (const int*)d_in[4];
    const float* eps_rp     = (const float*)d_in[5];
    const float* eps_rp0    = (const float*)d_in[6];
    const float* eps_rp1    = (const float*)d_in[7];
    const float* conv1_w    = (const float*)d_in[8];
    const float* conv1_b    = (const float*)d_in[9];
    const float* conv2_w    = (const float*)d_in[10];
    const float* conv2_b    = (const float*)d_in[11];
    const float* mlp_w1     = (const float*)d_in[12];
    const float* mlp_b1     = (const float*)d_in[13];
    const float* mlp_w2     = (const float*)d_in[14];
    const float* mlp_b2     = (const float*)d_in[15];
    const float* mlp_w3     = (const float*)d_in[16];
    const float* mlp_b3     = (const float*)d_in[17];
    const float* W_ih       = (const float*)d_in[18];
    const float* b_ih       = (const float*)d_in[19];
    const float* W_hh       = (const float*)d_in[20];
    const float* b_hh       = (const float*)d_in[21];
    const float* addr_emb   = (const float*)d_in[22];
    const float* pid_emb    = (const float*)d_in[23];
    const float* sid_emb    = (const float*)d_in[24];
    const float* pid_ext_w  = (const float*)d_in[25];
    const float* pid_ext_b  = (const float*)d_in[26];
    const float* sid_ext_w  = (const float*)d_in[27];
    const float* sid_ext_b  = (const float*)d_in[28];
    const float* rp_ext_w   = (const float*)d_in[29];
    const float* rp_ext_b   = (const float*)d_in[30];
    float* out = (float*)d_out;

    float *obs_part, *bias, *hb, *cb;
    __half *ws, *wo, *oe, *hh, *sp;
    uint8_t* w2p;
    cudaGetSymbolAddress((void**)&obs_part, g_obs_part);
    cudaGetSymbolAddress((void**)&bias,     g_bias);
    cudaGetSymbolAddress((void**)&hb,       g_hbuf);
    cudaGetSymbolAddress((void**)&cb,       g_cbuf);
    cudaGetSymbolAddress((void**)&ws,       g_Ws);
    cudaGetSymbolAddress((void**)&wo,       g_Wo);
    cudaGetSymbolAddress((void**)&oe,       g_obsE);
    cudaGetSymbolAddress((void**)&hh,       g_hh);
    cudaGetSymbolAddress((void**)&sp,       g_samp);
    cudaGetSymbolAddress((void**)&w2p,      g_w2pack);
    #define HBUF(i) (hb + (size_t)(i) * BATCH * HID)
    #define CBUF(i) (cb + (size_t)(i) * BATCH * HID)
    #define HH(i)   (hh + (size_t)(i) * BATCH * HID)
    #define SP(i)   (sp + (size_t)(i) * BATCH * 32)

    cudaFuncSetAttribute(encoder_kernel, cudaFuncAttributeMaxDynamicSharedMemorySize, ENC_SMEM_BYTES);
    cudaFuncSetAttribute(gemm_mma_kernel, cudaFuncAttributeMaxDynamicSharedMemorySize, GEMM_SMEM_BYTES);
    cudaFuncSetAttribute(headmlp_kernel, cudaFuncAttributeMaxDynamicSharedMemorySize, HM_SMEM_FLOATS * 4);

    // launch order: encoder is 4th -> profiled
    bias_kernel<<<7, 1024>>>(b_ih, b_hh, addr_emb, W_ih, bias);
    prep_ws_kernel<<<NB_WS, 256>>>(W_hh, W_ih, ws);
    prep_rest_kernel<<<NB_WO + 1 + NB_GA, 256>>>(W_ih, conv2_w,
                                                 program_id, shape_id, shape_id_0, shape_id_1,
                                                 pid_emb, sid_emb, wo, w2p, sp);
    encoder_kernel<<<BATCH / 4, 512, ENC_SMEM_BYTES>>>(obs, conv1_w, conv1_b, conv2_b, w2p, oe);

    dim3 ggrid(BATCH / 128, 8);
    // obs_part (mode 0)
    gemm_mma_kernel<<<ggrid, 256, GEMM_SMEM_BYTES>>>(oe, 416, 416, nullptr, wo, 416, 13, 0,
                                    nullptr, nullptr, nullptr, nullptr, obs_part, nullptr, nullptr);
    // h0,c0
    step0_kernel<<<(BATCH * 256 + 255) / 256, 256>>>(obs_part, bias, HBUF(0), CBUF(0), HH(0));
    // G12: dual-bias (aid1 -> idx1 h1, aid2 -> idx2 h1b), A=h0, samp=pid
    gemm_mma_kernel<<<ggrid, 256, GEMM_SMEM_BYTES>>>(HH(0), 256, 256, SP(0), ws, 288, 9, 2,
                                    obs_part, bias + 1 * 1024, bias + 2 * 1024, CBUF(0),
                                    HBUF(1), CBUF(1), HH(1));
    // G34: merged M=8192; A=[h1;h1b], samp=[sid;sid0], bias aid4 / aid3 -> [h2;h2b]
    {
        dim3 mg(2 * BATCH / 128, 8);
        gemm_mma_kernel<<<mg, 256, GEMM_SMEM_BYTES>>>(HH(1), 256, 256, SP(1), ws, 288, 9, 3,
                                    obs_part, bias + 4 * 1024, bias + 3 * 1024, CBUF(1),
                                    HBUF(3), CBUF(3), HH(3));
    }
    // step5: h3b = step(sid1, aid5, h2b=idx4) -> idx5
    gemm_mma_kernel<<<ggrid, 256, GEMM_SMEM_BYTES>>>(HH(4), 256, 256, SP(3), ws, 288, 9, 1,
                                    obs_part, bias + 5 * 1024, nullptr, CBUF(4),
                                    HBUF(5), CBUF(5), HH(5));
    // rp0 head + MLP fused
    headmlp_kernel<<<128, 256, HM_SMEM_FLOATS * 4>>>(HBUF(5), rp_ext_w, rp_ext_b, eps_rp0, out,
                                                     mlp_w1, mlp_b1, mlp_w2, mlp_b2,
                                                     mlp_w3, mlp_b3, SP(4));
    // step6: h4b = step(rp0emb, aid6, h3b=idx5) -> idx6
    gemm_mma_kernel<<<ggrid, 256, GEMM_SMEM_BYTES>>>(HH(5), 256, 256, SP(4), ws, 288, 9, 1,
                                    obs_part, bias + 6 * 1024, nullptr, CBUF(5),
                                    HBUF(6), CBUF(6), HH(6));
    // all remaining heads
    heads_kernel<<<128, 256>>>(hb, pid_ext_w, pid_ext_b, sid_ext_w, sid_ext_b,
                               rp_ext_w, rp_ext_b, eps_rp, eps_rp1, out);
}

// round 16
// speedup vs baseline: 1.1273x; 1.0489x over previous
#include <cuda_runtime.h>
#include <cuda_fp16.h>
#include <math.h>
#include <stdint.h>

#define BATCH 4096
#define HID 256

// ================= scratch (static device memory; zero-initialized) ==========
__device__ float g_obs_part[BATCH * 1024];
__device__ float g_bias[7 * 1024];
__device__ float g_cbuf[7][BATCH * HID];
__device__ __half g_obsE[BATCH * 416];
__device__ __half g_hh[7][BATCH * 256];
__device__ __half g_samp[5][BATCH * 32];
__device__ __half g_Ws[1024 * 288];
__device__ __half g_Wo[1024 * 416];
__device__ __align__(16) uint8_t g_w2pack[9216];

__device__ __forceinline__ uint32_t smem_to_u32(const void* p) {
    uint32_t a;
    asm("{ .reg .u64 t; cvta.to.shared.u64 t, %1; cvt.u32.u64 %0, t; }" : "=r"(a) : "l"(p));
    return a;
}

#define LDSM_X4(r0, r1, r2, r3, addr) \
    asm volatile("ldmatrix.sync.aligned.m8n8.x4.shared.b16 {%0,%1,%2,%3}, [%4];" \
                 : "=r"(r0), "=r"(r1), "=r"(r2), "=r"(r3) : "r"(addr))

#define CP16(dst, src) \
    asm volatile("cp.async.cg.shared.global [%0], [%1], 16;" :: "r"(dst), "l"(src))
#define CP_COMMIT() asm volatile("cp.async.commit_group;")
#define CP_WAIT0()  asm volatile("cp.async.wait_group 0;")
#define CP_WAIT1()  asm volatile("cp.async.wait_group 1;")

__device__ __forceinline__ void mma_f16(float* d, const uint32_t* a, const uint32_t* b) {
    asm volatile("mma.sync.aligned.m16n8k16.row.col.f32.f16.f16.f32 "
                 "{%0,%1,%2,%3}, {%4,%5,%6,%7}, {%8,%9}, {%0,%1,%2,%3};"
                 : "+f"(d[0]), "+f"(d[1]), "+f"(d[2]), "+f"(d[3])
                 : "r"(a[0]), "r"(a[1]), "r"(a[2]), "r"(a[3]), "r"(b[0]), "r"(b[1]));
}

__device__ __forceinline__ float tanh_fast(float x) {
    float e = __expf(2.f * x);
    return 1.f - __fdividef(2.f, e + 1.f);
}

__device__ __forceinline__ uint32_t pkh2(float a, float b) {
    __half2 h2 = __floats2half2_rn(a, b);
    return *reinterpret_cast<uint32_t*>(&h2);
}

__device__ __forceinline__ uint32_t swz32(uint32_t row, uint32_t chunk) {
    return row * 32u + ((chunk ^ ((row >> 2) & 1u)) << 4);
}
__device__ __forceinline__ uint32_t swz64(uint32_t row, uint32_t chunk) {
    return row * 64u + ((chunk ^ ((row >> 1) & 3u)) << 4);
}

// ================= fused prep: ws + wo + w2pack + gather + bias =================
#define NB_WS 1152
#define NB_WO 1664
#define NB_GA 256
#define NB_BI 28
#define NB_ALL (NB_WS + NB_WO + 1 + NB_GA + NB_BI)
__global__ void prep_all_kernel(const float* __restrict__ W_hh, const float* __restrict__ W_ih,
                                const float* __restrict__ c2w,
                                const int* __restrict__ pid, const int* __restrict__ sid,
                                const int* __restrict__ sid0, const int* __restrict__ sid1,
                                const float* __restrict__ pid_emb, const float* __restrict__ sid_emb,
                                const float* __restrict__ b_ih, const float* __restrict__ b_hh,
                                const float* __restrict__ addr_emb,
                                __half* __restrict__ ws, __half* __restrict__ wo,
                                uint8_t* __restrict__ w2pack, __half* __restrict__ sp,
                                float* __restrict__ bias)
{
    int b = blockIdx.x;
    int tid = threadIdx.x;
    if (b < NB_WS) {
        int idx = b * 256 + tid;
        int rr = idx / 288, k = idx % 288;
        int old = (rr & 3) * 256 + (rr >> 2);
        float v = 0.f;
        if (k < 256) v = W_hh[(size_t)old * 256 + k];
        else if (k < 272) v = W_ih[(size_t)old * 432 + 400 + (k - 256)];
        ws[idx] = __float2half_rn(v);
    } else if (b < NB_WS + NB_WO) {
        int idx = (b - NB_WS) * 256 + tid;
        int rr = idx / 416, k = idx % 416;
        int old = (rr & 3) * 256 + (rr >> 2);
        float v = (k < 400) ? W_ih[(size_t)old * 432 + k] : 0.f;
        wo[idx] = __float2half_rn(v);
    } else if (b == NB_WS + NB_WO) {
        for (int idx = tid; idx < 4608; idx += 256) {
            int cidx = idx >> 8;
            int koff = cidx >> 1, cih = cidx & 1;
            int rem = idx & 255;
            int co = rem >> 4, ci = rem & 15;
            float v = c2w[(co * 32 + cih * 16 + ci) * 9 + koff];
            uint32_t off = cidx * 512 + swz32(co, ci >> 3) + (ci & 7) * 2;
            *(__half*)(w2pack + off) = __float2half_rn(v);
        }
    } else if (b < NB_WS + NB_WO + 1 + NB_GA) {
        int t = (b - NB_WS - NB_WO - 1) * 256 + tid;
        int i = t >> 4, k = t & 15;
        int d = i * 32 + k;
        const size_t seg = (size_t)BATCH * 32;
        sp[d]           = __float2half_rn(pid_emb[pid[i] * 16 + k]);
        sp[seg + d]     = __float2half_rn(sid_emb[sid[i] * 16 + k]);
        sp[2 * seg + d] = __float2half_rn(sid_emb[sid0[i] * 16 + k]);
        sp[3 * seg + d] = __float2half_rn(sid_emb[sid1[i] * 16 + k]);
    } else {
        int idx = (b - NB_WS - NB_WO - 1 - NB_GA) * 256 + tid;   // 0..7167
        int aid = idx >> 10, r = idx & 1023;
        float s = b_ih[r] + b_hh[r];
        #pragma unroll
        for (int k = 0; k < 16; k++)
            s += addr_emb[aid * 16 + k] * W_ih[(size_t)r * 432 + 416 + k];
        int g = r >> 8, u = r & 255;
        bias[aid * 1024 + u * 4 + g] = s;
    }
}

// ================= encoder: fp16, 4 images/block, double-buffered img ===========
#define E_IMGA  0
#define E_IMGB  16384
#define E_C1    32768
#define E_W2    98304
#define E_ZERO  107520
#define ENC_SMEM_BYTES 107584

__global__ void __launch_bounds__(512, 2) encoder_kernel(
                               const float* __restrict__ obs,
                               const float* __restrict__ c1w, const float* __restrict__ c1b,
                               const float* __restrict__ c2b,
                               const uint8_t* __restrict__ w2pack,
                               __half* __restrict__ obs_emb)
{
    extern __shared__ __align__(16) char smem[];
    uint32_t sb = smem_to_u32(smem);
    int tid = threadIdx.x;
    int lane = tid & 31, w = tid >> 5;
    int img0 = blockIdx.x * 4;

    for (int i = tid; i < 576; i += 512) CP16(sb + E_W2 + i * 16, w2pack + i * 16);
    {
        const uint8_t* src = (const uint8_t*)(obs + (size_t)img0 * 4096);
        for (int i = tid; i < 1024; i += 512) CP16(sb + E_IMGA + i * 16, src + i * 16);
    }
    CP_COMMIT();
    if (tid < 4) ((uint4*)(smem + E_ZERO))[tid] = make_uint4(0, 0, 0, 0);

    int g = lane >> 2, cq = lane & 3;
    int k0c = 2 * cq, k1c = 2 * cq + 1;
    int ky0 = k0c / 3, kx0 = k0c % 3;
    int ky1 = k1c / 3, kx1 = k1c % 3;
    uint32_t b1[4][2];
    #pragma unroll
    for (int j = 0; j < 4; j++) {
        int n = j * 8 + g;
        b1[j][0] = pkh2(c1w[n * 9 + k0c], c1w[n * 9 + k1c]);
        b1[j][1] = pkh2((cq == 0) ? c1w[n * 9 + 8] : 0.f, 0.f);
    }
    float bia1a[4], bia1b[4];
    #pragma unroll
    for (int j = 0; j < 4; j++) {
        int cc = j * 8 + cq * 2;
        bia1a[j] = c1b[cc];
        bia1b[j] = c1b[cc + 1];
    }
    int p2 = w * 16 + (lane & 15);
    int oy2 = p2 >> 4, ox2 = p2 & 15;
    int khalf = lane >> 4;
    int nrow = (lane & 7) + ((lane >> 4) << 3);
    uint32_t chB = (lane >> 3) & 1;
    uint32_t boff = swz32(nrow, chB);
    uint32_t zbase = sb + (uint32_t)E_ZERO + (uint32_t)khalf * 16u;

    for (int it = 0; it < 4; it++) {
        int img = img0 + it;
        uint32_t curbuf = (it & 1) ? E_IMGB : E_IMGA;
        float* s_img = (float*)(smem + curbuf);
        CP_WAIT0();
        __syncthreads();

        #pragma unroll
        for (int t = 0; t < 4; t++) {
            int base = w * 64 + t * 16;
            int p0 = base + g, p1 = p0 + 8;
            int oy0 = p0 >> 5, ox0 = p0 & 31;
            int oy1 = p1 >> 5, ox1 = p1 & 31;
            int iy00 = 2 * oy0 - 1 + ky0, ix00 = 2 * ox0 - 1 + kx0;
            int iy01 = 2 * oy0 - 1 + ky1, ix01 = 2 * ox0 - 1 + kx1;
            int iy10 = 2 * oy1 - 1 + ky0, ix10 = 2 * ox1 - 1 + kx0;
            int iy11 = 2 * oy1 - 1 + ky1, ix11 = 2 * ox1 - 1 + kx1;
            float v00 = (iy00 >= 0 && ix00 >= 0) ? s_img[iy00 * 64 + ix00] : 0.f;
            float v01 = (iy01 >= 0 && ix01 >= 0) ? s_img[iy01 * 64 + ix01] : 0.f;
            float v10 = (iy10 >= 0 && ix10 >= 0) ? s_img[iy10 * 64 + ix10] : 0.f;
            float v11 = (iy11 >= 0 && ix11 >= 0) ? s_img[iy11 * 64 + ix11] : 0.f;
            float v08 = (cq == 0) ? s_img[(2 * oy0 + 1) * 64 + (2 * ox0 + 1)] : 0.f;
            float v18 = (cq == 0) ? s_img[(2 * oy1 + 1) * 64 + (2 * ox1 + 1)] : 0.f;
            uint32_t a[4];
            a[0] = pkh2(v00, v01);
            a[1] = pkh2(v10, v11);
            a[2] = pkh2(v08, 0.f);
            a[3] = pkh2(v18, 0.f);

            float acc[4][4];
            #pragma unroll
            for (int j = 0; j < 4; j++)
                #pragma unroll
                for (int q = 0; q < 4; q++) acc[j][q] = 0.f;
            #pragma unroll
            for (int j = 0; j < 4; j++) mma_f16(acc[j], a, b1[j]);

            #pragma unroll
            for (int j = 0; j < 4; j++) {
                #pragma unroll
                for (int rh = 0; rh < 2; rh++) {
                    int pos = base + g + rh * 8;
                    float v0 = fmaxf(acc[j][rh * 2 + 0] + bia1a[j], 0.f);
                    float v1 = fmaxf(acc[j][rh * 2 + 1] + bia1b[j], 0.f);
                    uint32_t addr = swz64((uint32_t)pos, (uint32_t)j) + cq * 4;
                    *(uint32_t*)(smem + E_C1 + addr) = pkh2(v0, v1);
                }
            }
        }
        __syncthreads();
        if (it < 3) {
            uint32_t nxtbuf = ((it + 1) & 1) ? E_IMGB : E_IMGA;
            const uint8_t* src = (const uint8_t*)(obs + (size_t)(img + 1) * 4096);
            for (int i = tid; i < 1024; i += 512) CP16(sb + nxtbuf + i * 16, src + i * 16);
            CP_COMMIT();
        }

        float acc2[2][4];
        #pragma unroll
        for (int j = 0; j < 2; j++)
            #pragma unroll
            for (int q = 0; q < 4; q++) acc2[j][q] = 0.f;
        #pragma unroll
        for (int koff = 0; koff < 9; koff++) {
            const int ky = koff / 3, kx = koff % 3;
            int iy = 2 * oy2 - 1 + ky, ix = 2 * ox2 - 1 + kx;
            bool valid = (iy >= 0 && iy < 32 && ix >= 0 && ix < 32);
            int c1pos = iy * 32 + ix;
            uint32_t rbase = (uint32_t)c1pos * 64u;
            uint32_t rx = ((uint32_t)(c1pos >> 1) & 3u) << 4;
            #pragma unroll
            for (int cih = 0; cih < 2; cih++) {
                uint32_t chunkA = (uint32_t)(cih * 2 + khalf);
                uint32_t offA = rbase + ((chunkA << 4) ^ rx);
                uint32_t aA = valid ? (sb + E_C1 + offA) : zbase;
                uint32_t bb = sb + (uint32_t)(E_W2) + (uint32_t)(koff * 2 + cih) * 512u + boff;
                uint32_t a[4], bh[2][2];
                LDSM_X4(a[0], a[1], a[2], a[3], aA);
                LDSM_X4(bh[0][0], bh[0][1], bh[1][0], bh[1][1], bb);
                mma_f16(acc2[0], a, bh[0]);
                mma_f16(acc2[1], a, bh[1]);
            }
        }
        {
            float* s_c2 = (float*)(smem + curbuf);
            #pragma unroll
            for (int j = 0; j < 2; j++) {
                int co = j * 8 + (lane & 3) * 2;
                float bia0 = c2b[co], bia1 = c2b[co + 1];
                #pragma unroll
                for (int rh = 0; rh < 2; rh++) {
                    int pos = w * 16 + (lane >> 2) + rh * 8;
                    float v0 = fmaxf(acc2[j][rh * 2 + 0] + bia0, 0.f);
                    float v1 = fmaxf(acc2[j][rh * 2 + 1] + bia1, 0.f);
                    *(float2*)(s_c2 + pos * 16 + co) = make_float2(v0, v1);
                }
            }
        }
        __syncthreads();
        {
            const float* s_c2 = (const float*)(smem + curbuf);
            if (tid < 400) {
                int c = tid / 25; int r = tid % 25; int i = r / 5; int j = r % 5;
                float s = 0.f;
                #pragma unroll
                for (int dy = 0; dy < 3; dy++)
                    #pragma unroll
                    for (int dx = 0; dx < 3; dx++)
                        s += s_c2[((3 * i + dy) * 16 + (3 * j + dx)) * 16 + c];
                obs_emb[(size_t)img * 416 + tid] = __float2half_rn(s * (1.f / 9.f));
            }
        }
        __syncthreads();
    }
}

// ====== mma.sync fp16 GEMM; 3-stage cp.async pipeline; modes 0 raw / 1 lstm / 2 dual / 3 merged ==
#define SROW 80
#define GBUF (128 * SROW)
#define GSTAGE (2 * GBUF)
#define GEMM_SMEM_BYTES (3 * GSTAGE)

__global__ void __launch_bounds__(256, 2) gemm_mma_kernel(
    const __half* __restrict__ A1, int strideA, int KA,
    const __half* __restrict__ S1,
    const __half* __restrict__ W1, int strideB,
    int nchunks, int mode,
    const float* __restrict__ obs_part, const float* __restrict__ bias,
    const float* __restrict__ bias_b,
    const float* __restrict__ c_in,
    float* __restrict__ outD, float* __restrict__ c_out,
    __half* __restrict__ h_out)
{
    extern __shared__ __align__(16) char smc[];
    uint32_t sb = smem_to_u32(smc);

    int tid = threadIdx.x;
    int lane = tid & 31, wid = tid >> 5;
    int wm = wid & 3, wn = wid >> 2;
    int m0 = blockIdx.x * 128;
    int n0 = blockIdx.y * 128;

    int lrow = tid >> 1, lhalf = tid & 1;
    const __half* A_row = A1 + (size_t)(m0 + lrow) * strideA;
    const __half* S_row = S1 ? S1 + (size_t)(m0 + lrow) * 32 : nullptr;
    const __half* W_row = W1 + (size_t)(n0 + lrow) * strideB;

    float acc[2][8][4];
    #pragma unroll
    for (int i = 0; i < 2; i++)
        #pragma unroll
        for (int j = 0; j < 8; j++)
            #pragma unroll
            for (int r = 0; r < 4; r++) acc[i][j][r] = 0.f;

    uint32_t dstA = lrow * SROW + lhalf * 32;

    auto prefetch = [&](int c, int stage) {
        uint32_t sbase = sb + stage * GSTAGE;
        int col = c * 32 + lhalf * 16;
        const __half* pa = (col < KA) ? (A_row + col) : (S_row + (col - KA));
        uint32_t ad = sbase + dstA;
        CP16(ad, pa); CP16(ad + 16, pa + 8);
        const __half* pw = W_row + c * 32 + lhalf * 16;
        CP16(ad + GBUF, pw); CP16(ad + GBUF + 16, pw + 8);
        CP_COMMIT();
    };

    prefetch(0, 0);
    if (nchunks > 1) prefetch(1, 1);

    int stage = 0;
    for (int c = 0; c < nchunks; c++) {
        CP_WAIT1();
        __syncthreads();
        if (c + 2 < nchunks) {
            int ps = stage + 2; if (ps >= 3) ps -= 3;
            prefetch(c + 2, ps);
        }

        uint32_t sbase = sb + stage * GSTAGE;
        uint32_t baseA = sbase, baseB = sbase + GBUF;

        #pragma unroll
        for (int s = 0; s < 2; s++) {
            uint32_t a[2][4], b[8][2];
            int rA = wm * 32 + (lane & 15);
            int cA = s * 32 + ((lane >> 4) << 4);
            uint32_t adA0 = rA * SROW + cA;
            uint32_t adA1 = (rA + 16) * SROW + cA;
            int rB = wn * 64 + ((lane >> 4) << 3) + (lane & 7);
            int cB = s * 32 + (((lane >> 3) & 1) << 4);

            LDSM_X4(a[0][0], a[0][1], a[0][2], a[0][3], baseA + adA0);
            LDSM_X4(a[1][0], a[1][1], a[1][2], a[1][3], baseA + adA1);
            #pragma unroll
            for (int p = 0; p < 4; p++)
                LDSM_X4(b[2 * p][0], b[2 * p][1], b[2 * p + 1][0], b[2 * p + 1][1],
                        baseB + (rB + 16 * p) * SROW + cB);
            #pragma unroll
            for (int mi = 0; mi < 2; mi++)
                #pragma unroll
                for (int nj = 0; nj < 8; nj++) mma_f16(acc[mi][nj], a[mi], b[nj]);
        }
        if (++stage >= 3) stage = 0;
    }

    #pragma unroll
    for (int mi = 0; mi < 2; mi++) {
        #pragma unroll
        for (int nj = 0; nj < 8; nj++) {
            int colg = n0 + wn * 64 + 8 * nj + 2 * (lane & 3);
            #pragma unroll
            for (int rh = 0; rh < 2; rh++) {
                int row = m0 + wm * 32 + mi * 16 + (lane >> 2) + 8 * rh;
                float v0 = acc[mi][nj][rh * 2 + 0];
                float v1 = acc[mi][nj][rh * 2 + 1];
                if (mode == 0) {
                    float2* dst = (float2*)(outD + (size_t)row * 1024 + colg);
                    *dst = make_float2(v0, v1);
                } else {
                    float2 op = *(const float2*)(obs_part + (size_t)(row & (BATCH - 1)) * 1024 + colg);
                    v0 += op.x;
                    v1 += op.y;
                    float g0 = __shfl_xor_sync(0xffffffffu, v0, 1);
                    float g1 = __shfl_xor_sync(0xffffffffu, v1, 1);
                    if ((lane & 1) == 0) {
                        int unit = colg >> 2;
                        float cprev = c_in[(size_t)row * 256 + unit];
                        size_t d = (size_t)row * 256 + unit;
                        const float* bp = (mode == 3 && row >= BATCH) ? bias_b : bias;
                        float4 b4 = *(const float4*)(bp + colg);
                        {
                            float gi = v0 + b4.x, gf = v1 + b4.y, gg = g0 + b4.z, go = g1 + b4.w;
                            float si = 1.f / (1.f + __expf(-gi));
                            float sf = 1.f / (1.f + __expf(-gf));
                            float so = 1.f / (1.f + __expf(-go));
                            float c2 = sf * cprev + si * tanh_fast(gg);
                            float hv = so * tanh_fast(c2);
                            c_out[d] = c2;
                            h_out[d] = __float2half_rn(hv);
                        }
                        if (mode == 2) {
                            float4 b4b = *(const float4*)(bias_b + colg);
                            size_t d2 = d + (size_t)BATCH * 256;
                            float gi = v0 + b4b.x, gf = v1 + b4b.y, gg = g0 + b4b.z, go = g1 + b4b.w;
                            float si = 1.f / (1.f + __expf(-gi));
                            float sf = 1.f / (1.f + __expf(-gf));
                            float so = 1.f / (1.f + __expf(-go));
                            float c2 = sf * cprev + si * tanh_fast(gg);
                            float hv = so * tanh_fast(c2);
                            c_out[d2] = c2;
                            h_out[d2] = __float2half_rn(hv);
                        }
                    }
                }
            }
        }
    }
}

// ================= step 0 =================
__global__ void step0_kernel(const float* __restrict__ op, const float* __restrict__ bias,
                             float* __restrict__ c, __half* __restrict__ h_h)
{
    int idx = blockIdx.x * blockDim.x + threadIdx.x;
    if (idx >= BATCH * 256) return;
    int row = idx >> 8, u = idx & 255;
    float4 o4 = ((const float4*)(op + (size_t)row * 1024))[u];
    float4 b4 = ((const float4*)bias)[u];
    float gi = o4.x + b4.x, gg = o4.z + b4.z, go = o4.w + b4.w;
    float si = 1.f / (1.f + __expf(-gi));
    float so = 1.f / (1.f + __expf(-go));
    float c2 = si * tanh_fast(gg);
    float hv = so * tanh_fast(c2);
    c[idx] = c2;
    h_h[idx] = __float2half_rn(hv);
}

// ================= fused rp0 head + MLP (reads fp16 h) =================
#define HM_SMEM_FLOATS (1024 + 4 + 64 + 200 + 104 + 100 * 101 + 104 + 16 * 101 + 16 + 2 * 32 * 104)
__global__ void headmlp_kernel(const __half* __restrict__ h, const float* __restrict__ W,
                               const float* __restrict__ bvec,
                               const float* __restrict__ eps, float* __restrict__ out,
                               const float* __restrict__ w1, const float* __restrict__ b1,
                               const float* __restrict__ w2, const float* __restrict__ b2,
                               const float* __restrict__ w3, const float* __restrict__ b3,
                               __half* __restrict__ emb)
{
    extern __shared__ float ms[];
    float* sWh = ms;
    float* sbh = sWh + 1024;
    float* srp = sbh + 4;
    float* sw1 = srp + 64;
    float* sb1 = sw1 + 200;
    float* sw2 = sb1 + 104;
    float* sb2 = sw2 + 100 * 101;
    float* sw3 = sb2 + 104;
    float* sb3 = sw3 + 16 * 101;
    float* z1  = sb3 + 16;
    float* z2  = z1 + 32 * 104;
    int tid = threadIdx.x;
    int lane = tid & 31, w = tid >> 5;
    int r0 = blockIdx.x * 32;

    for (int i = tid; i < 1024; i += 256) sWh[i] = W[i];
    if (tid < 4) sbh[tid] = bvec[tid];
    for (int i = tid; i < 200; i += 256) sw1[i] = w1[i];
    if (tid < 100) { sb1[tid] = b1[tid]; sb2[tid] = b2[tid]; }
    if (tid < 16) sb3[tid] = b3[tid];
    for (int i = tid; i < 10000; i += 256) { int u = i / 100, k = i - u * 100; sw2[u * 101 + k] = w2[i]; }
    for (int i = tid; i < 1600; i += 256) { int o = i / 100, k = i - o * 100; sw3[o * 101 + k] = w3[i]; }
    __syncthreads();

    for (int rr = 0; rr < 4; rr++) {
        int lrow = w * 4 + rr;
        int row = r0 + lrow;
        const __half* hp = h + (size_t)row * 256;
        float p0 = 0.f, p1 = 0.f, p2 = 0.f, p3 = 0.f;
        #pragma unroll
        for (int t = 0; t < 8; t++) {
            int k = lane + 32 * t;
            float hv = __half2float(hp[k]);
            p0 += hv * sWh[k];
            p1 += hv * sWh[256 + k];
            p2 += hv * sWh[512 + k];
            p3 += hv * sWh[768 + k];
        }
        #pragma unroll
        for (int o = 16; o; o >>= 1) {
            p0 += __shfl_xor_sync(0xffffffffu, p0, o);
            p1 += __shfl_xor_sync(0xffffffffu, p1, o);
            p2 += __shfl_xor_sync(0xffffffffu, p2, o);
            p3 += __shfl_xor_sync(0xffffffffu, p3, o);
        }
        if (lane == 0) {
            float v0 = p0 + sbh[0], v1 = p1 + sbh[1], v2 = p2 + sbh[2], v3 = p3 + sbh[3];
            float o0 = v0 + __expf(v2) * eps[row * 2 + 0];
            float o1 = v1 + __expf(v3) * eps[row * 2 + 1];
            out[(size_t)row * 15 + 11] = o0;
            out[(size_t)row * 15 + 12] = o1;
            srp[lrow * 2 + 0] = o0;
            srp[lrow * 2 + 1] = o1;
        }
    }
    __syncthreads();

    for (int t = tid; t < 3200; t += 256) {
        int row = t / 100, u = t - row * 100;
        float x0 = srp[row * 2], x1 = srp[row * 2 + 1];
        z1[row * 104 + u] = tanh_fast(sb1[u] + sw1[u * 2] * x0 + sw1[u * 2 + 1] * x1);
    }
    __syncthreads();
    for (int t = tid; t < 3200; t += 256) {
        int row = t / 100, u = t - row * 100;
        float s = sb2[u];
        const float* wr = sw2 + u * 101;
        const float* zr = z1 + row * 104;
        #pragma unroll 4
        for (int k = 0; k < 100; k++) s += wr[k] * zr[k];
        z2[row * 104 + u] = tanh_fast(s);
    }
    __syncthreads();
    for (int t = tid; t < 512; t += 256) {
        int row = t >> 4, o = t & 15;
        float s = sb3[o];
        const float* wr = sw3 + o * 101;
        const float* zr = z2 + row * 104;
        #pragma unroll 4
        for (int k = 0; k < 100; k++) s += wr[k] * zr[k];
        emb[(size_t)(r0 + row) * 32 + o] = __float2half_rn(s);
    }
}

// ================= mega head: 6 heads, reads fp16 h =================
__global__ void heads_kernel(const __half* __restrict__ hb,
                             const float* __restrict__ pid_w, const float* __restrict__ pid_b,
                             const float* __restrict__ sid_w, const float* __restrict__ sid_b,
                             const float* __restrict__ rp_w, const float* __restrict__ rp_b,
                             const float* __restrict__ eps_rp, const float* __restrict__ eps_rp1,
                             float* __restrict__ out)
{
    __shared__ float sW[2304];
    __shared__ float sB[12];
    int tid = threadIdx.x;
    int lane = tid & 31, w = tid >> 5;
    for (int i = tid; i < 768; i += 256) sW[i] = pid_w[i];
    for (int i = tid; i < 512; i += 256) sW[768 + i] = sid_w[i];
    for (int i = tid; i < 1024; i += 256) sW[1280 + i] = rp_w[i];
    if (tid < 3) sB[tid] = pid_b[tid];
    if (tid < 2) sB[4 + tid] = sid_b[tid];
    if (tid < 4) sB[8 + tid] = rp_b[tid];
    __syncthreads();

    const int Hidx[6] = {0, 1, 3, 2, 4, 6};
    const int Wof[6]  = {0, 768, 1280, 768, 768, 1280};
    const int Bof[6]  = {0, 4, 8, 4, 4, 8};
    const int Nout[6] = {3, 2, 4, 2, 2, 4};
    const int Off[6]  = {0, 3, 5, 7, 9, 13};

    int rowbase = blockIdx.x * 32 + w * 4;
    for (int rr = 0; rr < 4; rr++) {
        int row = rowbase + rr;
        #pragma unroll
        for (int e = 0; e < 6; e++) {
            const __half* hp = hb + (size_t)Hidx[e] * BATCH * 256 + (size_t)row * 256;
            int wof = Wof[e];
            float p0 = 0.f, p1 = 0.f, p2 = 0.f, p3 = 0.f;
            #pragma unroll
            for (int t = 0; t < 8; t++) {
                int k = lane + 32 * t;
                float hv = __half2float(hp[k]);
                p0 += hv * sW[wof + k];
                p1 += hv * sW[wof + 256 + k];
                if (Nout[e] > 2) p2 += hv * sW[wof + 512 + k];
                if (Nout[e] > 3) p3 += hv * sW[wof + 768 + k];
            }
            #pragma unroll
            for (int o = 16; o; o >>= 1) {
                p0 += __shfl_xor_sync(0xffffffffu, p0, o);
                p1 += __shfl_xor_sync(0xffffffffu, p1, o);
                p2 += __shfl_xor_sync(0xffffffffu, p2, o);
                p3 += __shfl_xor_sync(0xffffffffu, p3, o);
            }
            if (lane == 0) {
                int off = Off[e];
                float b0 = sB[Bof[e]], b1 = sB[Bof[e] + 1];
                if (Nout[e] == 4) {
                    const float* ee = (e == 2) ? eps_rp : eps_rp1;
                    float v0 = p0 + b0, v1 = p1 + b1;
                    float v2 = p2 + sB[Bof[e] + 2], v3 = p3 + sB[Bof[e] + 3];
                    out[(size_t)row * 15 + off + 0] = v0 + __expf(v2) * ee[row * 2 + 0];
                    out[(size_t)row * 15 + off + 1] = v1 + __expf(v3) * ee[row * 2 + 1];
                } else {
                    out[(size_t)row * 15 + off + 0] = p0 + b0;
                    out[(size_t)row * 15 + off + 1] = p1 + b1;
                    if (Nout[e] > 2) out[(size_t)row * 15 + off + 2] = p2 + sB[Bof[e] + 2];
                }
            }
        }
    }
}

// ================= launch =================
extern "C" void kernel_launch(void* const* d_in, const int* in_sizes, int n_in,
                              void* d_out, int out_size)
{
    const float* obs        = (const float*)d_in[0];
    const int*   program_id = (const int*)d_in[1];
    const int*   shape_id   = (const int*)d_in[2];
    const int*   shape_id_0 = (const int*)d_in[3];
    const int*   shape_id_1 = (const int*)d_in[4];
    const float* eps_rp     = (const float*)d_in[5];
    const float* eps_rp0    = (const float*)d_in[6];
    const float* eps_rp1    = (const float*)d_in[7];
    const float* conv1_w    = (const float*)d_in[8];
    const float* conv1_b    = (const float*)d_in[9];
    const float* conv2_w    = (const float*)d_in[10];
    const float* conv2_b    = (const float*)d_in[11];
    const float* mlp_w1     = (const float*)d_in[12];
    const float* mlp_b1     = (const float*)d_in[13];
    const float* mlp_w2     = (const float*)d_in[14];
    const float* mlp_b2     = (const float*)d_in[15];
    const float* mlp_w3     = (const float*)d_in[16];
    const float* mlp_b3     = (const float*)d_in[17];
    const float* W_ih       = (const float*)d_in[18];
    const float* b_ih       = (const float*)d_in[19];
    const float* W_hh       = (const float*)d_in[20];
    const float* b_hh       = (const float*)d_in[21];
    const float* addr_emb   = (const float*)d_in[22];
    const float* pid_emb    = (const float*)d_in[23];
    const float* sid_emb    = (const float*)d_in[24];
    const float* pid_ext_w  = (const float*)d_in[25];
    const float* pid_ext_b  = (const float*)d_in[26];
    const float* sid_ext_w  = (const float*)d_in[27];
    const float* sid_ext_b  = (const float*)d_in[28];
    const float* rp_ext_w   = (const float*)d_in[29];
    const float* rp_ext_b   = (const float*)d_in[30];
    float* out = (float*)d_out;

    float *obs_part, *bias, *cb;
    __half *ws, *wo, *oe, *hh, *sp;
    uint8_t* w2p;
    cudaGetSymbolAddress((void**)&obs_part, g_obs_part);
    cudaGetSymbolAddress((void**)&bias,     g_bias);
    cudaGetSymbolAddress((void**)&cb,       g_cbuf);
    cudaGetSymbolAddress((void**)&ws,       g_Ws);
    cudaGetSymbolAddress((void**)&wo,       g_Wo);
    cudaGetSymbolAddress((void**)&oe,       g_obsE);
    cudaGetSymbolAddress((void**)&hh,       g_hh);
    cudaGetSymbolAddress((void**)&sp,       g_samp);
    cudaGetSymbolAddress((void**)&w2p,      g_w2pack);
    #define CBUF(i) (cb + (size_t)(i) * BATCH * HID)
    #define HH(i)   (hh + (size_t)(i) * BATCH * HID)
    #define SP(i)   (sp + (size_t)(i) * BATCH * 32)

    cudaFuncSetAttribute(encoder_kernel, cudaFuncAttributeMaxDynamicSharedMemorySize, ENC_SMEM_BYTES);
    cudaFuncSetAttribute(gemm_mma_kernel, cudaFuncAttributeMaxDynamicSharedMemorySize, GEMM_SMEM_BYTES);
    cudaFuncSetAttribute(headmlp_kernel, cudaFuncAttributeMaxDynamicSharedMemorySize, HM_SMEM_FLOATS * 4);

    // 1: fused prep
    prep_all_kernel<<<NB_ALL, 256>>>(W_hh, W_ih, conv2_w,
                                     program_id, shape_id, shape_id_0, shape_id_1,
                                     pid_emb, sid_emb, b_ih, b_hh, addr_emb,
                                     ws, wo, w2p, sp, bias);
    // 2: encoder
    encoder_kernel<<<BATCH / 4, 512, ENC_SMEM_BYTES>>>(obs, conv1_w, conv1_b, conv2_b, w2p, oe);

    dim3 ggrid(BATCH / 128, 8);
    // 3: obs_part (mode 0)
    gemm_mma_kernel<<<ggrid, 256, GEMM_SMEM_BYTES>>>(oe, 416, 416, nullptr, wo, 416, 13, 0,
                                    nullptr, nullptr, nullptr, nullptr, obs_part, nullptr, nullptr);
    // 4: step0 (profiled)
    step0_kernel<<<(BATCH * 256 + 255) / 256, 256>>>(obs_part, bias, CBUF(0), HH(0));
    // 5: G12 dual-bias
    gemm_mma_kernel<<<ggrid, 256, GEMM_SMEM_BYTES>>>(HH(0), 256, 256, SP(0), ws, 288, 9, 2,
                                    obs_part, bias + 1 * 1024, bias + 2 * 1024, CBUF(0),
                                    nullptr, CBUF(1), HH(1));
    // 6: G34 merged M=8192
    {
        dim3 mg(2 * BATCH / 128, 8);
        gemm_mma_kernel<<<mg, 256, GEMM_SMEM_BYTES>>>(HH(1), 256, 256, SP(1), ws, 288, 9, 3,
                                    obs_part, bias + 4 * 1024, bias + 3 * 1024, CBUF(1),
                                    nullptr, CBUF(3), HH(3));
    }
    // 7: step5
    gemm_mma_kernel<<<ggrid, 256, GEMM_SMEM_BYTES>>>(HH(4), 256, 256, SP(3), ws, 288, 9, 1,
                                    obs_part, bias + 5 * 1024, nullptr, CBUF(4),
                                    nullptr, CBUF(5), HH(5));
    // 8: rp0 head + MLP fused (reads fp16 h5)
    headmlp_kernel<<<128, 256, HM_SMEM_FLOATS * 4>>>(HH(5), rp_ext_w, rp_ext_b, eps_rp0, out,
                                                     mlp_w1, mlp_b1, mlp_w2, mlp_b2,
                                                     mlp_w3, mlp_b3, SP(4));
    // 9: step6
    gemm_mma_kernel<<<ggrid, 256, GEMM_SMEM_BYTES>>>(HH(5), 256, 256, SP(4), ws, 288, 9, 1,
                                    obs_part, bias + 6 * 1024, nullptr, CBUF(5),
                                    nullptr, CBUF(6), HH(6));
    // 10: remaining heads (reads fp16 h)
    heads_kernel<<<128, 256>>>(hh, pid_ext_w, pid_ext_b, sid_ext_w, sid_ext_b,
                               rp_ext_w, rp_ext_b, eps_rp, eps_rp1, out);
}